// round 2
// baseline (speedup 1.0000x reference)
#include <cuda_runtime.h>

// ============================================================================
// GCN SAGE + graph-LayerNorm + residual, fp32 baseline.
// Phases (per layer): zero -> edge scatter-add (atomics) -> mean scale ->
//   fused dual GEMM (agg@Wl + h@Wr + b) with LN-stats epilogue -> LN apply+ReLU
// Layer 2's LN-apply adds the residual and writes d_out.
// NOTE: edge_index arrives as int32 (JAX x64 disabled).
// ============================================================================

#define NN 100000
#define CC 128

// Scratch (allocation-free: __device__ globals)
__device__ float  g_agg[NN * CC];    // edge-aggregated features
__device__ float  g_h1[NN * CC];     // layer-1 output (post LN+ReLU)
__device__ float  g_hpre[NN * CC];   // pre-LN buffer (both layers)
__device__ float  g_cnt[NN];         // in-degree counts
__device__ double g_stats[4];        // {sum,sumsq} x 2 layers

// ---------------------------------------------------------------------------
__global__ void zero_kernel(int statsBase, long long tot, int nrows) {
    long long i = (long long)blockIdx.x * blockDim.x + threadIdx.x;
    long long stride = (long long)gridDim.x * blockDim.x;
    for (long long t = i; t < tot; t += stride) g_agg[t] = 0.f;
    for (long long t = i; t < nrows; t += stride) g_cnt[t] = 0.f;
    if (i < 2) g_stats[statsBase + i] = 0.0;
}

// One warp per edge: 32 lanes x float4 = 128 channels.
__global__ void edge_kernel(const float* __restrict__ x,
                            const int* __restrict__ src,
                            const int* __restrict__ dst,
                            int E, int nrows, int useH1) {
    int w = (int)(((long long)blockIdx.x * blockDim.x + threadIdx.x) >> 5);
    if (w >= E) return;
    int lane = threadIdx.x & 31;
    const float* h = useH1 ? g_h1 : x;
    int s = src[w];
    int d = dst[w];
    if ((unsigned)s >= (unsigned)nrows || (unsigned)d >= (unsigned)nrows) return;
    float4 v = ((const float4*)(h + (size_t)s * CC))[lane];
    float* a = g_agg + (size_t)d * CC + lane * 4;
    atomicAdd(a + 0, v.x);
    atomicAdd(a + 1, v.y);
    atomicAdd(a + 2, v.z);
    atomicAdd(a + 3, v.w);
    if (lane == 0) atomicAdd(&g_cnt[d], 1.0f);
}

// agg[n, :] /= max(cnt[n], 1)
__global__ void scale_kernel(long long tot) {
    long long i = (long long)blockIdx.x * blockDim.x + threadIdx.x;
    long long stride = (long long)gridDim.x * blockDim.x;
    for (long long t = i; t < tot; t += stride) {
        float c = g_cnt[t >> 7];
        g_agg[t] *= 1.0f / fmaxf(c, 1.0f);
    }
}

// ---------------------------------------------------------------------------
// Fused dual GEMM: hpre = g_agg @ W0 + A1 @ W1 + bias   (K=128 each, N cols=128)
// BM=128 rows/block, 256 threads, 8x8 register tile split into 4x4 quads at
// {0,+64} offsets for conflict-free smem reads. LN stats (sum, sumsq) reduced
// per block into g_stats[statsBase..+1].
// ---------------------------------------------------------------------------
__global__ __launch_bounds__(256) void gemm_ln_kernel(
    const float* __restrict__ x,
    const float* __restrict__ W0, const float* __restrict__ W1,
    const float* __restrict__ bias,
    int statsBase, int nrows, int useH1)
{
    __shared__ float As[16][128];
    __shared__ float Ws[16][128];
    __shared__ double red[256];

    const float* A1 = useH1 ? g_h1 : x;

    int tid = threadIdx.x;
    int tx = tid & 15;        // column group
    int ty = tid >> 4;        // row group
    int rb = ty * 4;          // rows: rb+{0..3}, rb+64+{0..3}
    int cb = tx * 4;          // cols: cb+{0..3}, cb+64+{0..3}
    int row0 = blockIdx.x * 128;

    float acc[8][8];
#pragma unroll
    for (int i = 0; i < 8; i++)
#pragma unroll
        for (int j = 0; j < 8; j++) acc[i][j] = 0.f;

    for (int phase = 0; phase < 2; ++phase) {
        const float* A = phase ? A1 : g_agg;
        const float* W = phase ? W1 : W0;
        for (int k0 = 0; k0 < 128; k0 += 16) {
            __syncthreads();
#pragma unroll
            for (int j = 0; j < 2; ++j) {
                int idx = tid + j * 256;
                // A tile (transposed into As[k][m])
                int m = idx >> 2;
                int kq = (idx & 3) * 4;
                float4 va = make_float4(0.f, 0.f, 0.f, 0.f);
                int gr = row0 + m;
                if (gr < nrows)
                    va = *(const float4*)(A + (size_t)gr * 128 + k0 + kq);
                As[kq + 0][m] = va.x;
                As[kq + 1][m] = va.y;
                As[kq + 2][m] = va.z;
                As[kq + 3][m] = va.w;
                // W tile (row-major)
                int kw = idx >> 5;
                int c4 = idx & 31;
                ((float4*)Ws[kw])[c4] =
                    *(const float4*)(W + (size_t)(k0 + kw) * 128 + c4 * 4);
            }
            __syncthreads();
#pragma unroll
            for (int k = 0; k < 16; ++k) {
                float a[8], w[8];
                *(float4*)&a[0] = *(float4*)&As[k][rb];
                *(float4*)&a[4] = *(float4*)&As[k][rb + 64];
                *(float4*)&w[0] = *(float4*)&Ws[k][cb];
                *(float4*)&w[4] = *(float4*)&Ws[k][cb + 64];
#pragma unroll
                for (int i = 0; i < 8; i++)
#pragma unroll
                    for (int j = 0; j < 8; j++) acc[i][j] += a[i] * w[j];
            }
        }
    }

    // Epilogue: bias, store, LN stats
    float4 b0 = *(const float4*)&bias[cb];
    float4 b1 = *(const float4*)&bias[cb + 64];
    float bj[8] = {b0.x, b0.y, b0.z, b0.w, b1.x, b1.y, b1.z, b1.w};

    double s = 0.0, sq = 0.0;
#pragma unroll
    for (int ih = 0; ih < 2; ih++) {
#pragma unroll
        for (int i = 0; i < 4; i++) {
            int gr = row0 + rb + ih * 64 + i;
            if (gr < nrows) {
#pragma unroll
                for (int jh = 0; jh < 2; jh++) {
                    float4 v;
                    v.x = acc[ih * 4 + i][jh * 4 + 0] + bj[jh * 4 + 0];
                    v.y = acc[ih * 4 + i][jh * 4 + 1] + bj[jh * 4 + 1];
                    v.z = acc[ih * 4 + i][jh * 4 + 2] + bj[jh * 4 + 2];
                    v.w = acc[ih * 4 + i][jh * 4 + 3] + bj[jh * 4 + 3];
                    *(float4*)&g_hpre[(size_t)gr * 128 + cb + jh * 64] = v;
                    s += (double)v.x + (double)v.y + (double)v.z + (double)v.w;
                    sq += (double)v.x * v.x + (double)v.y * v.y +
                          (double)v.z * v.z + (double)v.w * v.w;
                }
            }
        }
    }

    __syncthreads();
    red[tid] = s;
    __syncthreads();
    for (int off = 128; off; off >>= 1) {
        if (tid < off) red[tid] += red[tid + off];
        __syncthreads();
    }
    if (tid == 0) atomicAdd(&g_stats[statsBase + 0], red[0]);
    __syncthreads();
    red[tid] = sq;
    __syncthreads();
    for (int off = 128; off; off >>= 1) {
        if (tid < off) red[tid] += red[tid + off];
        __syncthreads();
    }
    if (tid == 0) atomicAdd(&g_stats[statsBase + 1], red[0]);
}

// ---------------------------------------------------------------------------
// LN apply + ReLU (+ optional residual into external out buffer)
// ---------------------------------------------------------------------------
__global__ void ln_apply_kernel(const float* __restrict__ gamma,
                                const float* __restrict__ beta,
                                int statsBase,
                                const float* __restrict__ residual,
                                float* __restrict__ outExt,
                                long long total)
{
    double cntd = (double)total;
    double mu = g_stats[statsBase + 0] / cntd;
    double var = g_stats[statsBase + 1] / cntd - mu * mu;
    float rstd = (float)rsqrt(var + 1e-5);
    float fmu = (float)mu;

    long long n4 = total >> 2;
    long long i = (long long)blockIdx.x * blockDim.x + threadIdx.x;
    long long stride = (long long)gridDim.x * blockDim.x;
    float* out = outExt ? outExt : g_h1;

    for (long long t = i; t < n4; t += stride) {
        int cg = (int)(t & 31);   // which float4 within the 128-channel row
        float4 g = ((const float4*)gamma)[cg];
        float4 b = ((const float4*)beta)[cg];
        float4 h = ((const float4*)g_hpre)[t];
        float4 v;
        v.x = fmaxf((h.x - fmu) * rstd * g.x + b.x, 0.f);
        v.y = fmaxf((h.y - fmu) * rstd * g.y + b.y, 0.f);
        v.z = fmaxf((h.z - fmu) * rstd * g.z + b.z, 0.f);
        v.w = fmaxf((h.w - fmu) * rstd * g.w + b.w, 0.f);
        if (residual) {
            float4 r = ((const float4*)residual)[t];
            v.x += r.x; v.y += r.y; v.z += r.z; v.w += r.w;
        }
        ((float4*)out)[t] = v;
    }
}

// ---------------------------------------------------------------------------
extern "C" void kernel_launch(void* const* d_in, const int* in_sizes, int n_in,
                              void* d_out, int out_size)
{
    const float* x   = (const float*)d_in[0];
    const int*   ei  = (const int*)d_in[1];   // int32! (JAX x64 disabled)
    const float* Wl1 = (const float*)d_in[2];
    const float* bl1 = (const float*)d_in[3];
    const float* Wr1 = (const float*)d_in[4];
    const float* g1  = (const float*)d_in[5];
    const float* b1  = (const float*)d_in[6];
    const float* Wl2 = (const float*)d_in[7];
    const float* bl2 = (const float*)d_in[8];
    const float* Wr2 = (const float*)d_in[9];
    const float* g2  = (const float*)d_in[10];
    const float* b2  = (const float*)d_in[11];

    int E = in_sizes[1] / 2;
    int nrows = in_sizes[0] / CC;
    long long total = (long long)nrows * CC;

    const int* src = ei;
    const int* dst = ei + E;

    int edgeBlocks = (E + 7) / 8;          // warp per edge, 8 warps/block
    int gemmBlocks = (nrows + 127) / 128;
    int lnBlocks   = (int)((total / 4 + 255) / 256);

    // ---- Layer 1 ----
    zero_kernel<<<2048, 256>>>(0, total, nrows);
    edge_kernel<<<edgeBlocks, 256>>>(x, src, dst, E, nrows, 0);
    scale_kernel<<<2048, 256>>>(total);
    gemm_ln_kernel<<<gemmBlocks, 256>>>(x, Wl1, Wr1, bl1, 0, nrows, 0);
    ln_apply_kernel<<<lnBlocks, 256>>>(g1, b1, 0, nullptr, nullptr, total);

    // ---- Layer 2 ----
    zero_kernel<<<2048, 256>>>(2, total, nrows);
    edge_kernel<<<edgeBlocks, 256>>>(x, src, dst, E, nrows, 1);
    scale_kernel<<<2048, 256>>>(total);
    gemm_ln_kernel<<<gemmBlocks, 256>>>(x, Wl2, Wr2, bl2, 2, nrows, 1);
    ln_apply_kernel<<<lnBlocks, 256>>>(g2, b2, 2, x, (float*)d_out, total);
}

// round 4
// speedup vs baseline: 1.9974x; 1.9974x over previous
#include <cuda_runtime.h>

// ============================================================================
// GCN SAGE + graph-LayerNorm + residual.
// R3: CSR build (once) + gather-based mean aggregation (no float atomics).
// Per layer: agg(gather) -> fused dual GEMM + LN stats -> LN apply + ReLU.
// edge_index is int32 (JAX x64 disabled).
// ============================================================================

#define NN 100000
#define CC 128
#define EMAX 1600000

// Scratch (allocation-free: __device__ globals)
__device__ float  g_agg[NN * CC];     // mean-aggregated features
__device__ float  g_h1[NN * CC];      // layer-1 output (post LN+ReLU)
__device__ float  g_hpre[NN * CC];    // pre-LN buffer (both layers)
__device__ double g_stats[4];         // {sum,sumsq} x 2 layers
__device__ int    g_deg[NN];          // in-degree
__device__ int    g_off[NN + 1];      // CSR offsets (by dst)
__device__ int    g_pos[NN];          // fill cursors
__device__ int    g_eidx[EMAX];       // src ids bucketed by dst

// ---------------------------------------------------------------------------
// CSR build
// ---------------------------------------------------------------------------
__global__ void zero_misc_kernel(int nrows) {
    int i = blockIdx.x * blockDim.x + threadIdx.x;
    int stride = gridDim.x * blockDim.x;
    for (int t = i; t < nrows; t += stride) g_deg[t] = 0;
    if (i < 4) g_stats[i] = 0.0;
}

__global__ void hist_kernel(const int* __restrict__ dst, int E, int nrows) {
    int e = blockIdx.x * blockDim.x + threadIdx.x;
    if (e >= E) return;
    int d = dst[e];
    if ((unsigned)d < (unsigned)nrows) atomicAdd(&g_deg[d], 1);
}

// Single-block exclusive scan over g_deg -> g_off; zeroes g_pos.
__global__ void scan_kernel(int nrows) {
    __shared__ int part[1024];
    int t = threadIdx.x;
    int chunk = (nrows + 1023) / 1024;
    int beg = t * chunk;
    int end = min(beg + chunk, nrows);
    int s = 0;
    for (int i = beg; i < end; i++) s += g_deg[i];
    part[t] = s;
    __syncthreads();
    // inclusive scan of partials
    for (int off = 1; off < 1024; off <<= 1) {
        int v = (t >= off) ? part[t - off] : 0;
        __syncthreads();
        part[t] += v;
        __syncthreads();
    }
    int run = t ? part[t - 1] : 0;
    for (int i = beg; i < end; i++) {
        g_off[i] = run;
        g_pos[i] = 0;
        run += g_deg[i];
    }
    if (end == nrows && beg <= nrows) g_off[nrows] = run;
}

__global__ void fill_kernel(const int* __restrict__ src,
                            const int* __restrict__ dst, int E, int nrows) {
    int e = blockIdx.x * blockDim.x + threadIdx.x;
    if (e >= E) return;
    int d = dst[e];
    int s = src[e];
    if ((unsigned)d >= (unsigned)nrows || (unsigned)s >= (unsigned)nrows) return;
    int p = atomicAdd(&g_pos[d], 1);
    g_eidx[g_off[d] + p] = s;
}

// ---------------------------------------------------------------------------
// Gather aggregation: one warp per dst node; lane owns channels [lane*4, +4).
// agg[n] = mean of h[src] over incoming edges (0 if no edges).
// ---------------------------------------------------------------------------
__global__ __launch_bounds__(256) void agg_kernel(const float* __restrict__ x,
                                                  int nrows, int useH1) {
    int w = (int)(((long long)blockIdx.x * blockDim.x + threadIdx.x) >> 5);
    if (w >= nrows) return;
    int lane = threadIdx.x & 31;
    const float* __restrict__ h = useH1 ? g_h1 : x;

    int beg = g_off[w];
    int end = g_off[w + 1];
    float4 acc = make_float4(0.f, 0.f, 0.f, 0.f);

    int i = beg;
    for (; i + 2 <= end; i += 2) {
        int s0 = g_eidx[i];
        int s1 = g_eidx[i + 1];
        float4 v0 = ((const float4*)(h + (size_t)s0 * CC))[lane];
        float4 v1 = ((const float4*)(h + (size_t)s1 * CC))[lane];
        acc.x += v0.x + v1.x;
        acc.y += v0.y + v1.y;
        acc.z += v0.z + v1.z;
        acc.w += v0.w + v1.w;
    }
    if (i < end) {
        int s0 = g_eidx[i];
        float4 v0 = ((const float4*)(h + (size_t)s0 * CC))[lane];
        acc.x += v0.x; acc.y += v0.y; acc.z += v0.z; acc.w += v0.w;
    }

    float inv = 1.0f / fmaxf((float)(end - beg), 1.0f);
    acc.x *= inv; acc.y *= inv; acc.z *= inv; acc.w *= inv;
    ((float4*)(g_agg + (size_t)w * CC))[lane] = acc;
}

// ---------------------------------------------------------------------------
// Fused dual GEMM: hpre = g_agg @ W0 + A1 @ W1 + bias   (K=128, 128 cols)
// BM=128 rows/block, 256 threads, 8x8 register tile (4x4 quads at {0,+64}).
// LN stats (sum, sumsq) block-reduced into g_stats[statsBase..+1].
// ---------------------------------------------------------------------------
__global__ __launch_bounds__(256) void gemm_ln_kernel(
    const float* __restrict__ x,
    const float* __restrict__ W0, const float* __restrict__ W1,
    const float* __restrict__ bias,
    int statsBase, int nrows, int useH1)
{
    __shared__ float As[16][128];
    __shared__ float Ws[16][128];
    __shared__ double red[256];

    const float* A1 = useH1 ? g_h1 : x;

    int tid = threadIdx.x;
    int tx = tid & 15;
    int ty = tid >> 4;
    int rb = ty * 4;
    int cb = tx * 4;
    int row0 = blockIdx.x * 128;

    float acc[8][8];
#pragma unroll
    for (int i = 0; i < 8; i++)
#pragma unroll
        for (int j = 0; j < 8; j++) acc[i][j] = 0.f;

    for (int phase = 0; phase < 2; ++phase) {
        const float* A = phase ? A1 : g_agg;
        const float* W = phase ? W1 : W0;
        for (int k0 = 0; k0 < 128; k0 += 16) {
            __syncthreads();
#pragma unroll
            for (int j = 0; j < 2; ++j) {
                int idx = tid + j * 256;
                int m = idx >> 2;
                int kq = (idx & 3) * 4;
                float4 va = make_float4(0.f, 0.f, 0.f, 0.f);
                int gr = row0 + m;
                if (gr < nrows)
                    va = *(const float4*)(A + (size_t)gr * 128 + k0 + kq);
                As[kq + 0][m] = va.x;
                As[kq + 1][m] = va.y;
                As[kq + 2][m] = va.z;
                As[kq + 3][m] = va.w;
                int kw = idx >> 5;
                int c4 = idx & 31;
                ((float4*)Ws[kw])[c4] =
                    *(const float4*)(W + (size_t)(k0 + kw) * 128 + c4 * 4);
            }
            __syncthreads();
#pragma unroll
            for (int k = 0; k < 16; ++k) {
                float a[8], w[8];
                *(float4*)&a[0] = *(float4*)&As[k][rb];
                *(float4*)&a[4] = *(float4*)&As[k][rb + 64];
                *(float4*)&w[0] = *(float4*)&Ws[k][cb];
                *(float4*)&w[4] = *(float4*)&Ws[k][cb + 64];
#pragma unroll
                for (int i = 0; i < 8; i++)
#pragma unroll
                    for (int j = 0; j < 8; j++) acc[i][j] += a[i] * w[j];
            }
        }
    }

    float4 b0 = *(const float4*)&bias[cb];
    float4 b1 = *(const float4*)&bias[cb + 64];
    float bj[8] = {b0.x, b0.y, b0.z, b0.w, b1.x, b1.y, b1.z, b1.w};

    double s = 0.0, sq = 0.0;
#pragma unroll
    for (int ih = 0; ih < 2; ih++) {
#pragma unroll
        for (int i = 0; i < 4; i++) {
            int gr = row0 + rb + ih * 64 + i;
            if (gr < nrows) {
#pragma unroll
                for (int jh = 0; jh < 2; jh++) {
                    float4 v;
                    v.x = acc[ih * 4 + i][jh * 4 + 0] + bj[jh * 4 + 0];
                    v.y = acc[ih * 4 + i][jh * 4 + 1] + bj[jh * 4 + 1];
                    v.z = acc[ih * 4 + i][jh * 4 + 2] + bj[jh * 4 + 2];
                    v.w = acc[ih * 4 + i][jh * 4 + 3] + bj[jh * 4 + 3];
                    *(float4*)&g_hpre[(size_t)gr * 128 + cb + jh * 64] = v;
                    s += (double)v.x + (double)v.y + (double)v.z + (double)v.w;
                    sq += (double)v.x * v.x + (double)v.y * v.y +
                          (double)v.z * v.z + (double)v.w * v.w;
                }
            }
        }
    }

    __syncthreads();
    red[tid] = s;
    __syncthreads();
    for (int off = 128; off; off >>= 1) {
        if (tid < off) red[tid] += red[tid + off];
        __syncthreads();
    }
    if (tid == 0) atomicAdd(&g_stats[statsBase + 0], red[0]);
    __syncthreads();
    red[tid] = sq;
    __syncthreads();
    for (int off = 128; off; off >>= 1) {
        if (tid < off) red[tid] += red[tid + off];
        __syncthreads();
    }
    if (tid == 0) atomicAdd(&g_stats[statsBase + 1], red[0]);
}

// ---------------------------------------------------------------------------
// LN apply + ReLU (+ optional residual into external out buffer)
// ---------------------------------------------------------------------------
__global__ void ln_apply_kernel(const float* __restrict__ gamma,
                                const float* __restrict__ beta,
                                int statsBase,
                                const float* __restrict__ residual,
                                float* __restrict__ outExt,
                                long long total)
{
    double cntd = (double)total;
    double mu = g_stats[statsBase + 0] / cntd;
    double var = g_stats[statsBase + 1] / cntd - mu * mu;
    float rstd = (float)rsqrt(var + 1e-5);
    float fmu = (float)mu;

    long long n4 = total >> 2;
    long long i = (long long)blockIdx.x * blockDim.x + threadIdx.x;
    long long stride = (long long)gridDim.x * blockDim.x;
    float* out = outExt ? outExt : g_h1;

    for (long long t = i; t < n4; t += stride) {
        int cg = (int)(t & 31);
        float4 g = ((const float4*)gamma)[cg];
        float4 b = ((const float4*)beta)[cg];
        float4 h = ((const float4*)g_hpre)[t];
        float4 v;
        v.x = fmaxf((h.x - fmu) * rstd * g.x + b.x, 0.f);
        v.y = fmaxf((h.y - fmu) * rstd * g.y + b.y, 0.f);
        v.z = fmaxf((h.z - fmu) * rstd * g.z + b.z, 0.f);
        v.w = fmaxf((h.w - fmu) * rstd * g.w + b.w, 0.f);
        if (residual) {
            float4 r = ((const float4*)residual)[t];
            v.x += r.x; v.y += r.y; v.z += r.z; v.w += r.w;
        }
        ((float4*)out)[t] = v;
    }
}

// ---------------------------------------------------------------------------
extern "C" void kernel_launch(void* const* d_in, const int* in_sizes, int n_in,
                              void* d_out, int out_size)
{
    const float* x   = (const float*)d_in[0];
    const int*   ei  = (const int*)d_in[1];   // int32
    const float* Wl1 = (const float*)d_in[2];
    const float* bl1 = (const float*)d_in[3];
    const float* Wr1 = (const float*)d_in[4];
    const float* g1  = (const float*)d_in[5];
    const float* b1  = (const float*)d_in[6];
    const float* Wl2 = (const float*)d_in[7];
    const float* bl2 = (const float*)d_in[8];
    const float* Wr2 = (const float*)d_in[9];
    const float* g2  = (const float*)d_in[10];
    const float* b2  = (const float*)d_in[11];

    int E = in_sizes[1] / 2;
    int nrows = in_sizes[0] / CC;
    long long total = (long long)nrows * CC;

    const int* src = ei;
    const int* dst = ei + E;

    int eBlocks   = (E + 255) / 256;
    int aggBlocks = (nrows + 7) / 8;           // warp per node, 8 warps/block
    int gemmBlocks = (nrows + 127) / 128;
    int lnBlocks  = (int)((total / 4 + 255) / 256);

    // ---- CSR build (shared by both layers) ----
    zero_misc_kernel<<<256, 256>>>(nrows);
    hist_kernel<<<eBlocks, 256>>>(dst, E, nrows);
    scan_kernel<<<1, 1024>>>(nrows);
    fill_kernel<<<eBlocks, 256>>>(src, dst, E, nrows);

    // ---- Layer 1 ----
    agg_kernel<<<aggBlocks, 256>>>(x, nrows, 0);
    gemm_ln_kernel<<<gemmBlocks, 256>>>(x, Wl1, Wr1, bl1, 0, nrows, 0);
    ln_apply_kernel<<<lnBlocks, 256>>>(g1, b1, 0, nullptr, nullptr, total);

    // ---- Layer 2 ----
    agg_kernel<<<aggBlocks, 256>>>(x, nrows, 1);
    gemm_ln_kernel<<<gemmBlocks, 256>>>(x, Wl2, Wr2, bl2, 2, nrows, 1);
    ln_apply_kernel<<<lnBlocks, 256>>>(g2, b2, 2, x, (float*)d_out, total);
}

// round 5
// speedup vs baseline: 2.6746x; 1.3391x over previous
#include <cuda_runtime.h>
#include <cstdint>

// ============================================================================
// GCN SAGE + graph-LayerNorm + residual.
// R5: GEMM moved to TF32 tensor cores (mma.sync.m16n8k8), fp32 stats epilogue.
// CSR build (once) + gather aggregation unchanged from R3.
// ============================================================================

#define NN 100000
#define CC 128
#define EMAX 1600000

__device__ float  g_agg[NN * CC];
__device__ float  g_h1[NN * CC];
__device__ float  g_hpre[NN * CC];
__device__ double g_stats[4];
__device__ int    g_deg[NN];
__device__ int    g_off[NN + 1];
__device__ int    g_pos[NN];
__device__ int    g_eidx[EMAX];

// ---------------------------------------------------------------------------
// CSR build
// ---------------------------------------------------------------------------
__global__ void zero_misc_kernel(int nrows) {
    int i = blockIdx.x * blockDim.x + threadIdx.x;
    int stride = gridDim.x * blockDim.x;
    for (int t = i; t < nrows; t += stride) g_deg[t] = 0;
    if (i < 4) g_stats[i] = 0.0;
}

__global__ void hist_kernel(const int* __restrict__ dst, int E, int nrows) {
    int e = blockIdx.x * blockDim.x + threadIdx.x;
    if (e >= E) return;
    int d = dst[e];
    if ((unsigned)d < (unsigned)nrows) atomicAdd(&g_deg[d], 1);
}

__global__ void scan_kernel(int nrows) {
    __shared__ int part[1024];
    int t = threadIdx.x;
    int chunk = (nrows + 1023) / 1024;
    int beg = t * chunk;
    int end = min(beg + chunk, nrows);
    int s = 0;
    for (int i = beg; i < end; i++) s += g_deg[i];
    part[t] = s;
    __syncthreads();
    for (int off = 1; off < 1024; off <<= 1) {
        int v = (t >= off) ? part[t - off] : 0;
        __syncthreads();
        part[t] += v;
        __syncthreads();
    }
    int run = t ? part[t - 1] : 0;
    for (int i = beg; i < end; i++) {
        g_off[i] = run;
        g_pos[i] = 0;
        run += g_deg[i];
    }
    if (end == nrows && beg <= nrows) g_off[nrows] = run;
}

__global__ void fill_kernel(const int* __restrict__ src,
                            const int* __restrict__ dst, int E, int nrows) {
    int e = blockIdx.x * blockDim.x + threadIdx.x;
    if (e >= E) return;
    int d = dst[e];
    int s = src[e];
    if ((unsigned)d >= (unsigned)nrows || (unsigned)s >= (unsigned)nrows) return;
    int p = atomicAdd(&g_pos[d], 1);
    g_eidx[g_off[d] + p] = s;
}

// ---------------------------------------------------------------------------
// Gather aggregation: one warp per dst node; lane owns channels [lane*4, +4).
// ---------------------------------------------------------------------------
__global__ __launch_bounds__(256) void agg_kernel(const float* __restrict__ x,
                                                  int nrows, int useH1) {
    int w = (int)(((long long)blockIdx.x * blockDim.x + threadIdx.x) >> 5);
    if (w >= nrows) return;
    int lane = threadIdx.x & 31;
    const float* __restrict__ h = useH1 ? g_h1 : x;

    int beg = g_off[w];
    int end = g_off[w + 1];
    float4 acc = make_float4(0.f, 0.f, 0.f, 0.f);

    int i = beg;
    for (; i + 2 <= end; i += 2) {
        int s0 = g_eidx[i];
        int s1 = g_eidx[i + 1];
        float4 v0 = ((const float4*)(h + (size_t)s0 * CC))[lane];
        float4 v1 = ((const float4*)(h + (size_t)s1 * CC))[lane];
        acc.x += v0.x + v1.x;
        acc.y += v0.y + v1.y;
        acc.z += v0.z + v1.z;
        acc.w += v0.w + v1.w;
    }
    if (i < end) {
        int s0 = g_eidx[i];
        float4 v0 = ((const float4*)(h + (size_t)s0 * CC))[lane];
        acc.x += v0.x; acc.y += v0.y; acc.z += v0.z; acc.w += v0.w;
    }

    float inv = 1.0f / fmaxf((float)(end - beg), 1.0f);
    acc.x *= inv; acc.y *= inv; acc.z *= inv; acc.w *= inv;
    ((float4*)(g_agg + (size_t)w * CC))[lane] = acc;
}

// ---------------------------------------------------------------------------
// TF32 tensor-core fused dual GEMM + LN stats.
// hpre = [g_agg | A1] @ [W0 ; W1] + bias   (effective K=256, N=128)
// Block: 256 thr (8 warps, 4x2 warp grid), BM=128, BN=128, BK=16.
// Warp tile 32x64 -> 2 (m16) x 8 (n8) mma.m16n8k8 per k8 step.
// Smem rows padded to 136 floats: fragment-read banks (8k+g) cover all 32.
// ---------------------------------------------------------------------------
__device__ __forceinline__ uint32_t f2tf32(float x) {
    uint32_t r;
    asm("cvt.rna.tf32.f32 %0, %1;" : "=r"(r) : "f"(x));
    return r;
}

__device__ __forceinline__ void mma_tf32(float& d0, float& d1, float& d2, float& d3,
                                         uint32_t a0, uint32_t a1, uint32_t a2, uint32_t a3,
                                         uint32_t b0, uint32_t b1) {
    asm volatile(
        "mma.sync.aligned.m16n8k8.row.col.f32.tf32.tf32.f32 "
        "{%0,%1,%2,%3}, {%4,%5,%6,%7}, {%8,%9}, {%0,%1,%2,%3};"
        : "+f"(d0), "+f"(d1), "+f"(d2), "+f"(d3)
        : "r"(a0), "r"(a1), "r"(a2), "r"(a3), "r"(b0), "r"(b1));
}

#define LDP 136   // padded row length (+8 slots -> conflict-free frag reads)

__global__ __launch_bounds__(256) void gemm_ln_kernel(
    const float* __restrict__ x,
    const float* __restrict__ W0, const float* __restrict__ W1,
    const float* __restrict__ bias,
    int statsBase, int nrows, int useH1)
{
    __shared__ float As[16][LDP];   // [k][m], tf32 bit patterns
    __shared__ float Ws[16][LDP];   // [k][n], tf32 bit patterns
    __shared__ double red[256];

    const float* A1 = useH1 ? g_h1 : x;

    int tid = threadIdx.x;
    int lane = tid & 31;
    int wid = tid >> 5;
    int wm = (wid & 3) * 32;   // warp row base
    int wn = (wid >> 2) * 64;  // warp col base
    int g = lane >> 2;         // group id (0..7)
    int c = lane & 3;          // thread-in-group (0..3)
    int row0 = blockIdx.x * 128;

    float acc[2][8][4];
#pragma unroll
    for (int mt = 0; mt < 2; mt++)
#pragma unroll
        for (int nt = 0; nt < 8; nt++)
#pragma unroll
            for (int q = 0; q < 4; q++) acc[mt][nt][q] = 0.f;

    for (int phase = 0; phase < 2; ++phase) {
        const float* A = phase ? A1 : g_agg;
        const float* W = phase ? W1 : W0;
        for (int k0 = 0; k0 < 128; k0 += 16) {
            __syncthreads();
#pragma unroll
            for (int j = 0; j < 2; ++j) {
                int idx = tid + j * 256;
                // A tile -> As[k][m] (transposed, tf32)
                int m = idx >> 2;
                int kq = (idx & 3) * 4;
                float4 va = make_float4(0.f, 0.f, 0.f, 0.f);
                int gr = row0 + m;
                if (gr < nrows)
                    va = *(const float4*)(A + (size_t)gr * 128 + k0 + kq);
                As[kq + 0][m] = __uint_as_float(f2tf32(va.x));
                As[kq + 1][m] = __uint_as_float(f2tf32(va.y));
                As[kq + 2][m] = __uint_as_float(f2tf32(va.z));
                As[kq + 3][m] = __uint_as_float(f2tf32(va.w));
                // W tile -> Ws[k][n] (row-major, tf32)
                int kw = idx >> 5;
                int c4 = idx & 31;
                float4 wv = *(const float4*)(W + (size_t)(k0 + kw) * 128 + c4 * 4);
                float4 wt;
                wt.x = __uint_as_float(f2tf32(wv.x));
                wt.y = __uint_as_float(f2tf32(wv.y));
                wt.z = __uint_as_float(f2tf32(wv.z));
                wt.w = __uint_as_float(f2tf32(wv.w));
                *(float4*)&Ws[kw][c4 * 4] = wt;
            }
            __syncthreads();
#pragma unroll
            for (int ks = 0; ks < 16; ks += 8) {
                uint32_t af[2][4];
#pragma unroll
                for (int mt = 0; mt < 2; mt++) {
                    int r = wm + mt * 16 + g;
                    af[mt][0] = __float_as_uint(As[ks + c][r]);
                    af[mt][1] = __float_as_uint(As[ks + c][r + 8]);
                    af[mt][2] = __float_as_uint(As[ks + c + 4][r]);
                    af[mt][3] = __float_as_uint(As[ks + c + 4][r + 8]);
                }
                uint32_t bf[8][2];
#pragma unroll
                for (int nt = 0; nt < 8; nt++) {
                    int n = wn + nt * 8 + g;
                    bf[nt][0] = __float_as_uint(Ws[ks + c][n]);
                    bf[nt][1] = __float_as_uint(Ws[ks + c + 4][n]);
                }
#pragma unroll
                for (int mt = 0; mt < 2; mt++)
#pragma unroll
                    for (int nt = 0; nt < 8; nt++)
                        mma_tf32(acc[mt][nt][0], acc[mt][nt][1],
                                 acc[mt][nt][2], acc[mt][nt][3],
                                 af[mt][0], af[mt][1], af[mt][2], af[mt][3],
                                 bf[nt][0], bf[nt][1]);
            }
        }
    }

    // Epilogue: bias + store + LN stats (fp32 per-thread, double block-reduce)
    float s = 0.f, sq = 0.f;
#pragma unroll
    for (int mt = 0; mt < 2; mt++) {
        int r0g = row0 + wm + mt * 16 + g;       // rows r0g, r0g+8
#pragma unroll
        for (int nt = 0; nt < 8; nt++) {
            int col = wn + nt * 8 + 2 * c;
            float2 bj = *(const float2*)&bias[col];
            float v0 = acc[mt][nt][0] + bj.x;
            float v1 = acc[mt][nt][1] + bj.y;
            float v2 = acc[mt][nt][2] + bj.x;
            float v3 = acc[mt][nt][3] + bj.y;
            if (r0g < nrows) {
                *(float2*)&g_hpre[(size_t)r0g * 128 + col] = make_float2(v0, v1);
                s += v0 + v1;
                sq += v0 * v0 + v1 * v1;
            }
            if (r0g + 8 < nrows) {
                *(float2*)&g_hpre[(size_t)(r0g + 8) * 128 + col] = make_float2(v2, v3);
                s += v2 + v3;
                sq += v2 * v2 + v3 * v3;
            }
        }
    }

    __syncthreads();
    red[tid] = (double)s;
    __syncthreads();
    for (int off = 128; off; off >>= 1) {
        if (tid < off) red[tid] += red[tid + off];
        __syncthreads();
    }
    if (tid == 0) atomicAdd(&g_stats[statsBase + 0], red[0]);
    __syncthreads();
    red[tid] = (double)sq;
    __syncthreads();
    for (int off = 128; off; off >>= 1) {
        if (tid < off) red[tid] += red[tid + off];
        __syncthreads();
    }
    if (tid == 0) atomicAdd(&g_stats[statsBase + 1], red[0]);
}

// ---------------------------------------------------------------------------
// LN apply + ReLU (+ optional residual into external out buffer)
// ---------------------------------------------------------------------------
__global__ void ln_apply_kernel(const float* __restrict__ gamma,
                                const float* __restrict__ beta,
                                int statsBase,
                                const float* __restrict__ residual,
                                float* __restrict__ outExt,
                                long long total)
{
    double cntd = (double)total;
    double mu = g_stats[statsBase + 0] / cntd;
    double var = g_stats[statsBase + 1] / cntd - mu * mu;
    float rstd = (float)rsqrt(var + 1e-5);
    float fmu = (float)mu;

    long long n4 = total >> 2;
    long long i = (long long)blockIdx.x * blockDim.x + threadIdx.x;
    long long stride = (long long)gridDim.x * blockDim.x;
    float* out = outExt ? outExt : g_h1;

    for (long long t = i; t < n4; t += stride) {
        int cg = (int)(t & 31);
        float4 g = ((const float4*)gamma)[cg];
        float4 b = ((const float4*)beta)[cg];
        float4 h = ((const float4*)g_hpre)[t];
        float4 v;
        v.x = fmaxf((h.x - fmu) * rstd * g.x + b.x, 0.f);
        v.y = fmaxf((h.y - fmu) * rstd * g.y + b.y, 0.f);
        v.z = fmaxf((h.z - fmu) * rstd * g.z + b.z, 0.f);
        v.w = fmaxf((h.w - fmu) * rstd * g.w + b.w, 0.f);
        if (residual) {
            float4 r = ((const float4*)residual)[t];
            v.x += r.x; v.y += r.y; v.z += r.z; v.w += r.w;
        }
        ((float4*)out)[t] = v;
    }
}

// ---------------------------------------------------------------------------
extern "C" void kernel_launch(void* const* d_in, const int* in_sizes, int n_in,
                              void* d_out, int out_size)
{
    const float* x   = (const float*)d_in[0];
    const int*   ei  = (const int*)d_in[1];   // int32
    const float* Wl1 = (const float*)d_in[2];
    const float* bl1 = (const float*)d_in[3];
    const float* Wr1 = (const float*)d_in[4];
    const float* g1  = (const float*)d_in[5];
    const float* b1  = (const float*)d_in[6];
    const float* Wl2 = (const float*)d_in[7];
    const float* bl2 = (const float*)d_in[8];
    const float* Wr2 = (const float*)d_in[9];
    const float* g2  = (const float*)d_in[10];
    const float* b2  = (const float*)d_in[11];

    int E = in_sizes[1] / 2;
    int nrows = in_sizes[0] / CC;
    long long total = (long long)nrows * CC;

    const int* src = ei;
    const int* dst = ei + E;

    int eBlocks    = (E + 255) / 256;
    int aggBlocks  = (nrows + 7) / 8;
    int gemmBlocks = (nrows + 127) / 128;
    int lnBlocks   = (int)((total / 4 + 255) / 256);

    // ---- CSR build (shared by both layers) ----
    zero_misc_kernel<<<256, 256>>>(nrows);
    hist_kernel<<<eBlocks, 256>>>(dst, E, nrows);
    scan_kernel<<<1, 1024>>>(nrows);
    fill_kernel<<<eBlocks, 256>>>(src, dst, E, nrows);

    // ---- Layer 1 ----
    agg_kernel<<<aggBlocks, 256>>>(x, nrows, 0);
    gemm_ln_kernel<<<gemmBlocks, 256>>>(x, Wl1, Wr1, bl1, 0, nrows, 0);
    ln_apply_kernel<<<lnBlocks, 256>>>(g1, b1, 0, nullptr, nullptr, total);

    // ---- Layer 2 ----
    agg_kernel<<<aggBlocks, 256>>>(x, nrows, 1);
    gemm_ln_kernel<<<gemmBlocks, 256>>>(x, Wl2, Wr2, bl2, 2, nrows, 1);
    ln_apply_kernel<<<lnBlocks, 256>>>(g2, b2, 2, x, (float*)d_out, total);
}

// round 7
// speedup vs baseline: 2.7689x; 1.0352x over previous
#include <cuda_runtime.h>
#include <cuda_fp16.h>
#include <cstdint>

// ============================================================================
// GCN SAGE + graph-LayerNorm + residual.
// R7: R6 with the K-loop bug fixed (16 K-tiles: phase = t>>3, k0 = (t&7)*16).
// fp16 gather source + double-buffered TF32 tensor GEMM.
// ============================================================================

#define NN 100000
#define CC 128
#define EMAX 1600000

__device__ float  g_agg[NN * CC];     // fp32 aggregated features
__device__ __half g_xh[NN * CC];      // x in fp16 (gather source, layer 1)
__device__ __half g_h1h[NN * CC];     // h1 in fp16 (gather + GEMM source, layer 2)
__device__ float  g_hpre[NN * CC];    // pre-LN buffer
__device__ double g_stats[4];
__device__ int    g_deg[NN];
__device__ int    g_off[NN + 1];
__device__ int    g_pos[NN];
__device__ int    g_eidx[EMAX];

// ---------------------------------------------------------------------------
// CSR build + x->half conversion
// ---------------------------------------------------------------------------
__global__ void zero_misc_kernel(int nrows) {
    int i = blockIdx.x * blockDim.x + threadIdx.x;
    int stride = gridDim.x * blockDim.x;
    for (int t = i; t < nrows; t += stride) g_deg[t] = 0;
    if (i < 4) g_stats[i] = 0.0;
}

__global__ void x2h_kernel(const float* __restrict__ x, long long n4) {
    long long i = (long long)blockIdx.x * blockDim.x + threadIdx.x;
    long long stride = (long long)gridDim.x * blockDim.x;
    for (long long t = i; t < n4; t += stride) {
        float4 v = ((const float4*)x)[t];
        __half2 h0 = __floats2half2_rn(v.x, v.y);
        __half2 h1 = __floats2half2_rn(v.z, v.w);
        uint2 u;
        u.x = *reinterpret_cast<uint32_t*>(&h0);
        u.y = *reinterpret_cast<uint32_t*>(&h1);
        ((uint2*)g_xh)[t] = u;
    }
}

__global__ void hist_kernel(const int* __restrict__ dst, int E, int nrows) {
    int e = blockIdx.x * blockDim.x + threadIdx.x;
    if (e >= E) return;
    int d = dst[e];
    if ((unsigned)d < (unsigned)nrows) atomicAdd(&g_deg[d], 1);
}

__global__ void scan_kernel(int nrows) {
    __shared__ int part[1024];
    int t = threadIdx.x;
    int chunk = (nrows + 1023) / 1024;
    int beg = t * chunk;
    int end = min(beg + chunk, nrows);
    int s = 0;
    for (int i = beg; i < end; i++) s += g_deg[i];
    part[t] = s;
    __syncthreads();
    for (int off = 1; off < 1024; off <<= 1) {
        int v = (t >= off) ? part[t - off] : 0;
        __syncthreads();
        part[t] += v;
        __syncthreads();
    }
    int run = t ? part[t - 1] : 0;
    for (int i = beg; i < end; i++) {
        g_off[i] = run;
        g_pos[i] = 0;
        run += g_deg[i];
    }
    if (end == nrows && beg <= nrows) g_off[nrows] = run;
}

__global__ void fill_kernel(const int* __restrict__ src,
                            const int* __restrict__ dst, int E, int nrows) {
    int e = blockIdx.x * blockDim.x + threadIdx.x;
    if (e >= E) return;
    int d = dst[e];
    int s = src[e];
    if ((unsigned)d >= (unsigned)nrows || (unsigned)s >= (unsigned)nrows) return;
    int p = atomicAdd(&g_pos[d], 1);
    g_eidx[g_off[d] + p] = s;
}

// ---------------------------------------------------------------------------
// Gather aggregation (fp16 source): one warp per dst node;
// lane owns channels [lane*4, +4).
// ---------------------------------------------------------------------------
__global__ __launch_bounds__(256) void agg_kernel(int nrows, int useH1) {
    int w = (int)(((long long)blockIdx.x * blockDim.x + threadIdx.x) >> 5);
    if (w >= nrows) return;
    int lane = threadIdx.x & 31;
    const __half* __restrict__ h = useH1 ? g_h1h : g_xh;
    const __half* base = h + (size_t)lane * 4;

    int beg = g_off[w];
    int end = g_off[w + 1];
    float4 acc = make_float4(0.f, 0.f, 0.f, 0.f);

    int i = beg;
    for (; i + 2 <= end; i += 2) {
        int s0 = g_eidx[i];
        int s1 = g_eidx[i + 1];
        uint2 r0 = *(const uint2*)(base + (size_t)s0 * CC);
        uint2 r1 = *(const uint2*)(base + (size_t)s1 * CC);
        float2 a0 = __half22float2(*reinterpret_cast<__half2*>(&r0.x));
        float2 a1 = __half22float2(*reinterpret_cast<__half2*>(&r0.y));
        float2 b0 = __half22float2(*reinterpret_cast<__half2*>(&r1.x));
        float2 b1 = __half22float2(*reinterpret_cast<__half2*>(&r1.y));
        acc.x += a0.x + b0.x;
        acc.y += a0.y + b0.y;
        acc.z += a1.x + b1.x;
        acc.w += a1.y + b1.y;
    }
    if (i < end) {
        int s0 = g_eidx[i];
        uint2 r0 = *(const uint2*)(base + (size_t)s0 * CC);
        float2 a0 = __half22float2(*reinterpret_cast<__half2*>(&r0.x));
        float2 a1 = __half22float2(*reinterpret_cast<__half2*>(&r0.y));
        acc.x += a0.x; acc.y += a0.y; acc.z += a1.x; acc.w += a1.y;
    }

    float inv = 1.0f / fmaxf((float)(end - beg), 1.0f);
    acc.x *= inv; acc.y *= inv; acc.z *= inv; acc.w *= inv;
    ((float4*)(g_agg + (size_t)w * CC))[lane] = acc;
}

// ---------------------------------------------------------------------------
// TF32 tensor-core fused dual GEMM + LN stats, double-buffered smem.
// hpre = [g_agg | A1] @ [W0 ; W1] + bias   (16 K-tiles of BK=16, N=128)
// ---------------------------------------------------------------------------
__device__ __forceinline__ uint32_t f2tf32(float x) {
    uint32_t r;
    asm("cvt.rna.tf32.f32 %0, %1;" : "=r"(r) : "f"(x));
    return r;
}
__device__ __forceinline__ float tf32f(float x) {
    return __uint_as_float(f2tf32(x));
}

__device__ __forceinline__ void mma_tf32(float& d0, float& d1, float& d2, float& d3,
                                         uint32_t a0, uint32_t a1, uint32_t a2, uint32_t a3,
                                         uint32_t b0, uint32_t b1) {
    asm volatile(
        "mma.sync.aligned.m16n8k8.row.col.f32.tf32.tf32.f32 "
        "{%0,%1,%2,%3}, {%4,%5,%6,%7}, {%8,%9}, {%0,%1,%2,%3};"
        : "+f"(d0), "+f"(d1), "+f"(d2), "+f"(d3)
        : "r"(a0), "r"(a1), "r"(a2), "r"(a3), "r"(b0), "r"(b1));
}

#define LDP 136
#define NTILES 16   // 2 phases x 8 K-tiles (BK=16, K=128 each)

__global__ __launch_bounds__(256) void gemm_ln_kernel(
    const float* __restrict__ x,
    const float* __restrict__ W0, const float* __restrict__ W1,
    const float* __restrict__ bias,
    int statsBase, int nrows, int useH1)
{
    __shared__ float As[2][16][LDP];
    __shared__ float Ws[2][16][LDP];
    __shared__ double red[256];

    int tid = threadIdx.x;
    int lane = tid & 31;
    int wid = tid >> 5;
    int wm = (wid & 3) * 32;
    int wn = (wid >> 2) * 64;
    int g = lane >> 2;
    int c = lane & 3;
    int row0 = blockIdx.x * 128;

    float acc[2][8][4];
#pragma unroll
    for (int mt = 0; mt < 2; mt++)
#pragma unroll
        for (int nt = 0; nt < 8; nt++)
#pragma unroll
            for (int q = 0; q < 4; q++) acc[mt][nt][q] = 0.f;

    float4 va[2], wv[2];

    auto load_tile = [&](int t) {
        int phase = t >> 3;            // 0: agg@W0, 1: A1@W1
        int k0 = (t & 7) * 16;         // full K=128 coverage
        const float* W = phase ? W1 : W0;
#pragma unroll
        for (int j = 0; j < 2; ++j) {
            int idx = tid + j * 256;
            int m = idx >> 2;
            int kq = (idx & 3) * 4;
            int gr = row0 + m;
            float4 v = make_float4(0.f, 0.f, 0.f, 0.f);
            if (gr < nrows) {
                if (phase == 0) {
                    v = *(const float4*)(g_agg + (size_t)gr * 128 + k0 + kq);
                } else if (!useH1) {
                    v = *(const float4*)(x + (size_t)gr * 128 + k0 + kq);
                } else {
                    uint2 hv = *(const uint2*)(g_h1h + (size_t)gr * 128 + k0 + kq);
                    float2 f0 = __half22float2(*reinterpret_cast<__half2*>(&hv.x));
                    float2 f1 = __half22float2(*reinterpret_cast<__half2*>(&hv.y));
                    v = make_float4(f0.x, f0.y, f1.x, f1.y);
                }
            }
            va[j] = v;
            int kw = idx >> 5;
            int c4 = idx & 31;
            wv[j] = *(const float4*)(W + (size_t)(k0 + kw) * 128 + c4 * 4);
        }
    };

    auto store_tile = [&](int buf) {
#pragma unroll
        for (int j = 0; j < 2; ++j) {
            int idx = tid + j * 256;
            int m = idx >> 2;
            int kq = (idx & 3) * 4;
            As[buf][kq + 0][m] = tf32f(va[j].x);
            As[buf][kq + 1][m] = tf32f(va[j].y);
            As[buf][kq + 2][m] = tf32f(va[j].z);
            As[buf][kq + 3][m] = tf32f(va[j].w);
            int kw = idx >> 5;
            int c4 = idx & 31;
            float4 wt;
            wt.x = tf32f(wv[j].x);
            wt.y = tf32f(wv[j].y);
            wt.z = tf32f(wv[j].z);
            wt.w = tf32f(wv[j].w);
            *(float4*)&Ws[buf][kw][c4 * 4] = wt;
        }
    };

    load_tile(0);
    store_tile(0);
    __syncthreads();

    for (int t = 0; t < NTILES; ++t) {
        int buf = t & 1;
        if (t < NTILES - 1) load_tile(t + 1);
#pragma unroll
        for (int ks = 0; ks < 16; ks += 8) {
            uint32_t af[2][4];
#pragma unroll
            for (int mt = 0; mt < 2; mt++) {
                int r = wm + mt * 16 + g;
                af[mt][0] = __float_as_uint(As[buf][ks + c][r]);
                af[mt][1] = __float_as_uint(As[buf][ks + c][r + 8]);
                af[mt][2] = __float_as_uint(As[buf][ks + c + 4][r]);
                af[mt][3] = __float_as_uint(As[buf][ks + c + 4][r + 8]);
            }
            uint32_t bf[8][2];
#pragma unroll
            for (int nt = 0; nt < 8; nt++) {
                int n = wn + nt * 8 + g;
                bf[nt][0] = __float_as_uint(Ws[buf][ks + c][n]);
                bf[nt][1] = __float_as_uint(Ws[buf][ks + c + 4][n]);
            }
#pragma unroll
            for (int mt = 0; mt < 2; mt++)
#pragma unroll
                for (int nt = 0; nt < 8; nt++)
                    mma_tf32(acc[mt][nt][0], acc[mt][nt][1],
                             acc[mt][nt][2], acc[mt][nt][3],
                             af[mt][0], af[mt][1], af[mt][2], af[mt][3],
                             bf[nt][0], bf[nt][1]);
        }
        if (t < NTILES - 1) store_tile(buf ^ 1);
        __syncthreads();
    }

    // Epilogue: bias + store + LN stats
    float s = 0.f, sq = 0.f;
#pragma unroll
    for (int mt = 0; mt < 2; mt++) {
        int r0g = row0 + wm + mt * 16 + g;
#pragma unroll
        for (int nt = 0; nt < 8; nt++) {
            int col = wn + nt * 8 + 2 * c;
            float2 bj = *(const float2*)&bias[col];
            float v0 = acc[mt][nt][0] + bj.x;
            float v1 = acc[mt][nt][1] + bj.y;
            float v2 = acc[mt][nt][2] + bj.x;
            float v3 = acc[mt][nt][3] + bj.y;
            if (r0g < nrows) {
                *(float2*)&g_hpre[(size_t)r0g * 128 + col] = make_float2(v0, v1);
                s += v0 + v1;
                sq += v0 * v0 + v1 * v1;
            }
            if (r0g + 8 < nrows) {
                *(float2*)&g_hpre[(size_t)(r0g + 8) * 128 + col] = make_float2(v2, v3);
                s += v2 + v3;
                sq += v2 * v2 + v3 * v3;
            }
        }
    }

    __syncthreads();
    red[tid] = (double)s;
    __syncthreads();
    for (int off = 128; off; off >>= 1) {
        if (tid < off) red[tid] += red[tid + off];
        __syncthreads();
    }
    if (tid == 0) atomicAdd(&g_stats[statsBase + 0], red[0]);
    __syncthreads();
    red[tid] = (double)sq;
    __syncthreads();
    for (int off = 128; off; off >>= 1) {
        if (tid < off) red[tid] += red[tid + off];
        __syncthreads();
    }
    if (tid == 0) atomicAdd(&g_stats[statsBase + 1], red[0]);
}

// ---------------------------------------------------------------------------
// LN apply + ReLU. toHalf: write g_h1h (fp16). Else: fp32 out + residual.
// ---------------------------------------------------------------------------
__global__ void ln_apply_kernel(const float* __restrict__ gamma,
                                const float* __restrict__ beta,
                                int statsBase,
                                const float* __restrict__ residual,
                                float* __restrict__ outExt,
                                int toHalf, long long total)
{
    double cntd = (double)total;
    double mu = g_stats[statsBase + 0] / cntd;
    double var = g_stats[statsBase + 1] / cntd - mu * mu;
    float rstd = (float)rsqrt(var + 1e-5);
    float fmu = (float)mu;

    long long n4 = total >> 2;
    long long i = (long long)blockIdx.x * blockDim.x + threadIdx.x;
    long long stride = (long long)gridDim.x * blockDim.x;

    for (long long t = i; t < n4; t += stride) {
        int cg = (int)(t & 31);
        float4 g = ((const float4*)gamma)[cg];
        float4 b = ((const float4*)beta)[cg];
        float4 h = ((const float4*)g_hpre)[t];
        float4 v;
        v.x = fmaxf((h.x - fmu) * rstd * g.x + b.x, 0.f);
        v.y = fmaxf((h.y - fmu) * rstd * g.y + b.y, 0.f);
        v.z = fmaxf((h.z - fmu) * rstd * g.z + b.z, 0.f);
        v.w = fmaxf((h.w - fmu) * rstd * g.w + b.w, 0.f);
        if (toHalf) {
            __half2 h0 = __floats2half2_rn(v.x, v.y);
            __half2 h1 = __floats2half2_rn(v.z, v.w);
            uint2 u;
            u.x = *reinterpret_cast<uint32_t*>(&h0);
            u.y = *reinterpret_cast<uint32_t*>(&h1);
            ((uint2*)g_h1h)[t] = u;
        } else {
            float4 r = ((const float4*)residual)[t];
            v.x += r.x; v.y += r.y; v.z += r.z; v.w += r.w;
            ((float4*)outExt)[t] = v;
        }
    }
}

// ---------------------------------------------------------------------------
extern "C" void kernel_launch(void* const* d_in, const int* in_sizes, int n_in,
                              void* d_out, int out_size)
{
    const float* x   = (const float*)d_in[0];
    const int*   ei  = (const int*)d_in[1];   // int32
    const float* Wl1 = (const float*)d_in[2];
    const float* bl1 = (const float*)d_in[3];
    const float* Wr1 = (const float*)d_in[4];
    const float* g1  = (const float*)d_in[5];
    const float* b1  = (const float*)d_in[6];
    const float* Wl2 = (const float*)d_in[7];
    const float* bl2 = (const float*)d_in[8];
    const float* Wr2 = (const float*)d_in[9];
    const float* g2  = (const float*)d_in[10];
    const float* b2  = (const float*)d_in[11];

    int E = in_sizes[1] / 2;
    int nrows = in_sizes[0] / CC;
    long long total = (long long)nrows * CC;

    const int* src = ei;
    const int* dst = ei + E;

    int eBlocks    = (E + 255) / 256;
    int aggBlocks  = (nrows + 7) / 8;
    int gemmBlocks = (nrows + 127) / 128;
    int lnBlocks   = (int)((total / 4 + 255) / 256);

    // ---- CSR build + x->half ----
    zero_misc_kernel<<<256, 256>>>(nrows);
    x2h_kernel<<<1024, 256>>>(x, total / 4);
    hist_kernel<<<eBlocks, 256>>>(dst, E, nrows);
    scan_kernel<<<1, 1024>>>(nrows);
    fill_kernel<<<eBlocks, 256>>>(src, dst, E, nrows);

    // ---- Layer 1 ----
    agg_kernel<<<aggBlocks, 256>>>(nrows, 0);
    gemm_ln_kernel<<<gemmBlocks, 256>>>(x, Wl1, Wr1, bl1, 0, nrows, 0);
    ln_apply_kernel<<<lnBlocks, 256>>>(g1, b1, 0, nullptr, nullptr, 1, total);

    // ---- Layer 2 ----
    agg_kernel<<<aggBlocks, 256>>>(nrows, 1);
    gemm_ln_kernel<<<gemmBlocks, 256>>>(x, Wl2, Wr2, bl2, 2, nrows, 1);
    ln_apply_kernel<<<lnBlocks, 256>>>(g2, b2, 2, x, (float*)d_out, 0, total);
}

// round 9
// speedup vs baseline: 4.0734x; 1.4711x over previous
#include <cuda_runtime.h>
#include <cuda_fp16.h>
#include <cstdint>

// ============================================================================
// GCN SAGE + graph-LayerNorm + residual.
// R8: parallel 3-phase CSR scan (was: 169us single-block scan).
// fp16 gather source + double-buffered TF32 tensor GEMM (from R7).
// ============================================================================

#define NN 100000
#define CC 128
#define EMAX 1600000
#define SCAN_BLK 1024

__device__ float  g_agg[NN * CC];     // fp32 aggregated features
__device__ __half g_xh[NN * CC];      // x in fp16 (gather source, layer 1)
__device__ __half g_h1h[NN * CC];     // h1 in fp16 (gather + GEMM source, layer 2)
__device__ float  g_hpre[NN * CC];    // pre-LN buffer
__device__ double g_stats[4];
__device__ int    g_deg[NN];
__device__ int    g_off[NN + 1];
__device__ int    g_pos[NN];
__device__ int    g_eidx[EMAX];
__device__ int    g_bsum[SCAN_BLK];   // per-block sums for the scan

// ---------------------------------------------------------------------------
// CSR build + x->half conversion
// ---------------------------------------------------------------------------
__global__ void zero_misc_kernel(int nrows) {
    int i = blockIdx.x * blockDim.x + threadIdx.x;
    int stride = gridDim.x * blockDim.x;
    for (int t = i; t < nrows; t += stride) g_deg[t] = 0;
    if (i < 4) g_stats[i] = 0.0;
}

__global__ void x2h_kernel(const float* __restrict__ x, long long n4) {
    long long i = (long long)blockIdx.x * blockDim.x + threadIdx.x;
    long long stride = (long long)gridDim.x * blockDim.x;
    for (long long t = i; t < n4; t += stride) {
        float4 v = ((const float4*)x)[t];
        __half2 h0 = __floats2half2_rn(v.x, v.y);
        __half2 h1 = __floats2half2_rn(v.z, v.w);
        uint2 u;
        u.x = *reinterpret_cast<uint32_t*>(&h0);
        u.y = *reinterpret_cast<uint32_t*>(&h1);
        ((uint2*)g_xh)[t] = u;
    }
}

__global__ void hist_kernel(const int* __restrict__ dst, int E, int nrows) {
    int e = blockIdx.x * blockDim.x + threadIdx.x;
    if (e >= E) return;
    int d = dst[e];
    if ((unsigned)d < (unsigned)nrows) atomicAdd(&g_deg[d], 1);
}

// Phase 1: per-block exclusive scan (coalesced), block totals to g_bsum.
__global__ __launch_bounds__(SCAN_BLK) void scan1_kernel(int nrows) {
    __shared__ int sm[SCAN_BLK];
    int t = threadIdx.x;
    int i = blockIdx.x * SCAN_BLK + t;
    int v = (i < nrows) ? g_deg[i] : 0;
    sm[t] = v;
    __syncthreads();
    for (int off = 1; off < SCAN_BLK; off <<= 1) {
        int u = (t >= off) ? sm[t - off] : 0;
        __syncthreads();
        sm[t] += u;
        __syncthreads();
    }
    if (i < nrows) {
        g_off[i] = sm[t] - v;   // exclusive, block-local
        g_pos[i] = 0;
    }
    if (t == SCAN_BLK - 1) g_bsum[blockIdx.x] = sm[t];
}

// Phase 2: scan the block sums (nblocks <= SCAN_BLK); write total to g_off[nrows].
__global__ __launch_bounds__(SCAN_BLK) void scan2_kernel(int nblocks, int nrows) {
    __shared__ int sm[SCAN_BLK];
    int t = threadIdx.x;
    int v = (t < nblocks) ? g_bsum[t] : 0;
    sm[t] = v;
    __syncthreads();
    for (int off = 1; off < SCAN_BLK; off <<= 1) {
        int u = (t >= off) ? sm[t - off] : 0;
        __syncthreads();
        sm[t] += u;
        __syncthreads();
    }
    if (t < nblocks) g_bsum[t] = sm[t] - v;   // exclusive
    if (t == SCAN_BLK - 1) g_off[nrows] = sm[t];
}

// Phase 3: add scanned block offsets.
__global__ __launch_bounds__(SCAN_BLK) void scan3_kernel(int nrows) {
    int i = blockIdx.x * SCAN_BLK + threadIdx.x;
    if (i < nrows && blockIdx.x > 0) g_off[i] += g_bsum[blockIdx.x];
}

__global__ void fill_kernel(const int* __restrict__ src,
                            const int* __restrict__ dst, int E, int nrows) {
    int e = blockIdx.x * blockDim.x + threadIdx.x;
    if (e >= E) return;
    int d = dst[e];
    int s = src[e];
    if ((unsigned)d >= (unsigned)nrows || (unsigned)s >= (unsigned)nrows) return;
    int p = atomicAdd(&g_pos[d], 1);
    g_eidx[g_off[d] + p] = s;
}

// ---------------------------------------------------------------------------
// Gather aggregation (fp16 source): one warp per dst node;
// lane owns channels [lane*4, +4).
// ---------------------------------------------------------------------------
__global__ __launch_bounds__(256) void agg_kernel(int nrows, int useH1) {
    int w = (int)(((long long)blockIdx.x * blockDim.x + threadIdx.x) >> 5);
    if (w >= nrows) return;
    int lane = threadIdx.x & 31;
    const __half* __restrict__ h = useH1 ? g_h1h : g_xh;
    const __half* base = h + (size_t)lane * 4;

    int beg = g_off[w];
    int end = g_off[w + 1];
    float4 acc = make_float4(0.f, 0.f, 0.f, 0.f);

    int i = beg;
    for (; i + 2 <= end; i += 2) {
        int s0 = g_eidx[i];
        int s1 = g_eidx[i + 1];
        uint2 r0 = *(const uint2*)(base + (size_t)s0 * CC);
        uint2 r1 = *(const uint2*)(base + (size_t)s1 * CC);
        float2 a0 = __half22float2(*reinterpret_cast<__half2*>(&r0.x));
        float2 a1 = __half22float2(*reinterpret_cast<__half2*>(&r0.y));
        float2 b0 = __half22float2(*reinterpret_cast<__half2*>(&r1.x));
        float2 b1 = __half22float2(*reinterpret_cast<__half2*>(&r1.y));
        acc.x += a0.x + b0.x;
        acc.y += a0.y + b0.y;
        acc.z += a1.x + b1.x;
        acc.w += a1.y + b1.y;
    }
    if (i < end) {
        int s0 = g_eidx[i];
        uint2 r0 = *(const uint2*)(base + (size_t)s0 * CC);
        float2 a0 = __half22float2(*reinterpret_cast<__half2*>(&r0.x));
        float2 a1 = __half22float2(*reinterpret_cast<__half2*>(&r0.y));
        acc.x += a0.x; acc.y += a0.y; acc.z += a1.x; acc.w += a1.y;
    }

    float inv = 1.0f / fmaxf((float)(end - beg), 1.0f);
    acc.x *= inv; acc.y *= inv; acc.z *= inv; acc.w *= inv;
    ((float4*)(g_agg + (size_t)w * CC))[lane] = acc;
}

// ---------------------------------------------------------------------------
// TF32 tensor-core fused dual GEMM + LN stats, double-buffered smem.
// ---------------------------------------------------------------------------
__device__ __forceinline__ uint32_t f2tf32(float x) {
    uint32_t r;
    asm("cvt.rna.tf32.f32 %0, %1;" : "=r"(r) : "f"(x));
    return r;
}
__device__ __forceinline__ float tf32f(float x) {
    return __uint_as_float(f2tf32(x));
}

__device__ __forceinline__ void mma_tf32(float& d0, float& d1, float& d2, float& d3,
                                         uint32_t a0, uint32_t a1, uint32_t a2, uint32_t a3,
                                         uint32_t b0, uint32_t b1) {
    asm volatile(
        "mma.sync.aligned.m16n8k8.row.col.f32.tf32.tf32.f32 "
        "{%0,%1,%2,%3}, {%4,%5,%6,%7}, {%8,%9}, {%0,%1,%2,%3};"
        : "+f"(d0), "+f"(d1), "+f"(d2), "+f"(d3)
        : "r"(a0), "r"(a1), "r"(a2), "r"(a3), "r"(b0), "r"(b1));
}

#define LDP 136
#define NTILES 16   // 2 phases x 8 K-tiles (BK=16, K=128 each)

__global__ __launch_bounds__(256) void gemm_ln_kernel(
    const float* __restrict__ x,
    const float* __restrict__ W0, const float* __restrict__ W1,
    const float* __restrict__ bias,
    int statsBase, int nrows, int useH1)
{
    __shared__ float As[2][16][LDP];
    __shared__ float Ws[2][16][LDP];
    __shared__ double red[256];

    int tid = threadIdx.x;
    int lane = tid & 31;
    int wid = tid >> 5;
    int wm = (wid & 3) * 32;
    int wn = (wid >> 2) * 64;
    int g = lane >> 2;
    int c = lane & 3;
    int row0 = blockIdx.x * 128;

    float acc[2][8][4];
#pragma unroll
    for (int mt = 0; mt < 2; mt++)
#pragma unroll
        for (int nt = 0; nt < 8; nt++)
#pragma unroll
            for (int q = 0; q < 4; q++) acc[mt][nt][q] = 0.f;

    float4 va[2], wv[2];

    auto load_tile = [&](int t) {
        int phase = t >> 3;
        int k0 = (t & 7) * 16;
        const float* W = phase ? W1 : W0;
#pragma unroll
        for (int j = 0; j < 2; ++j) {
            int idx = tid + j * 256;
            int m = idx >> 2;
            int kq = (idx & 3) * 4;
            int gr = row0 + m;
            float4 v = make_float4(0.f, 0.f, 0.f, 0.f);
            if (gr < nrows) {
                if (phase == 0) {
                    v = *(const float4*)(g_agg + (size_t)gr * 128 + k0 + kq);
                } else if (!useH1) {
                    v = *(const float4*)(x + (size_t)gr * 128 + k0 + kq);
                } else {
                    uint2 hv = *(const uint2*)(g_h1h + (size_t)gr * 128 + k0 + kq);
                    float2 f0 = __half22float2(*reinterpret_cast<__half2*>(&hv.x));
                    float2 f1 = __half22float2(*reinterpret_cast<__half2*>(&hv.y));
                    v = make_float4(f0.x, f0.y, f1.x, f1.y);
                }
            }
            va[j] = v;
            int kw = idx >> 5;
            int c4 = idx & 31;
            wv[j] = *(const float4*)(W + (size_t)(k0 + kw) * 128 + c4 * 4);
        }
    };

    auto store_tile = [&](int buf) {
#pragma unroll
        for (int j = 0; j < 2; ++j) {
            int idx = tid + j * 256;
            int m = idx >> 2;
            int kq = (idx & 3) * 4;
            As[buf][kq + 0][m] = tf32f(va[j].x);
            As[buf][kq + 1][m] = tf32f(va[j].y);
            As[buf][kq + 2][m] = tf32f(va[j].z);
            As[buf][kq + 3][m] = tf32f(va[j].w);
            int kw = idx >> 5;
            int c4 = idx & 31;
            float4 wt;
            wt.x = tf32f(wv[j].x);
            wt.y = tf32f(wv[j].y);
            wt.z = tf32f(wv[j].z);
            wt.w = tf32f(wv[j].w);
            *(float4*)&Ws[buf][kw][c4 * 4] = wt;
        }
    };

    load_tile(0);
    store_tile(0);
    __syncthreads();

    for (int t = 0; t < NTILES; ++t) {
        int buf = t & 1;
        if (t < NTILES - 1) load_tile(t + 1);
#pragma unroll
        for (int ks = 0; ks < 16; ks += 8) {
            uint32_t af[2][4];
#pragma unroll
            for (int mt = 0; mt < 2; mt++) {
                int r = wm + mt * 16 + g;
                af[mt][0] = __float_as_uint(As[buf][ks + c][r]);
                af[mt][1] = __float_as_uint(As[buf][ks + c][r + 8]);
                af[mt][2] = __float_as_uint(As[buf][ks + c + 4][r]);
                af[mt][3] = __float_as_uint(As[buf][ks + c + 4][r + 8]);
            }
            uint32_t bf[8][2];
#pragma unroll
            for (int nt = 0; nt < 8; nt++) {
                int n = wn + nt * 8 + g;
                bf[nt][0] = __float_as_uint(Ws[buf][ks + c][n]);
                bf[nt][1] = __float_as_uint(Ws[buf][ks + c + 4][n]);
            }
#pragma unroll
            for (int mt = 0; mt < 2; mt++)
#pragma unroll
                for (int nt = 0; nt < 8; nt++)
                    mma_tf32(acc[mt][nt][0], acc[mt][nt][1],
                             acc[mt][nt][2], acc[mt][nt][3],
                             af[mt][0], af[mt][1], af[mt][2], af[mt][3],
                             bf[nt][0], bf[nt][1]);
        }
        if (t < NTILES - 1) store_tile(buf ^ 1);
        __syncthreads();
    }

    // Epilogue: bias + store + LN stats
    float s = 0.f, sq = 0.f;
#pragma unroll
    for (int mt = 0; mt < 2; mt++) {
        int r0g = row0 + wm + mt * 16 + g;
#pragma unroll
        for (int nt = 0; nt < 8; nt++) {
            int col = wn + nt * 8 + 2 * c;
            float2 bj = *(const float2*)&bias[col];
            float v0 = acc[mt][nt][0] + bj.x;
            float v1 = acc[mt][nt][1] + bj.y;
            float v2 = acc[mt][nt][2] + bj.x;
            float v3 = acc[mt][nt][3] + bj.y;
            if (r0g < nrows) {
                *(float2*)&g_hpre[(size_t)r0g * 128 + col] = make_float2(v0, v1);
                s += v0 + v1;
                sq += v0 * v0 + v1 * v1;
            }
            if (r0g + 8 < nrows) {
                *(float2*)&g_hpre[(size_t)(r0g + 8) * 128 + col] = make_float2(v2, v3);
                s += v2 + v3;
                sq += v2 * v2 + v3 * v3;
            }
        }
    }

    __syncthreads();
    red[tid] = (double)s;
    __syncthreads();
    for (int off = 128; off; off >>= 1) {
        if (tid < off) red[tid] += red[tid + off];
        __syncthreads();
    }
    if (tid == 0) atomicAdd(&g_stats[statsBase + 0], red[0]);
    __syncthreads();
    red[tid] = (double)sq;
    __syncthreads();
    for (int off = 128; off; off >>= 1) {
        if (tid < off) red[tid] += red[tid + off];
        __syncthreads();
    }
    if (tid == 0) atomicAdd(&g_stats[statsBase + 1], red[0]);
}

// ---------------------------------------------------------------------------
// LN apply + ReLU. toHalf: write g_h1h (fp16). Else: fp32 out + residual.
// ---------------------------------------------------------------------------
__global__ void ln_apply_kernel(const float* __restrict__ gamma,
                                const float* __restrict__ beta,
                                int statsBase,
                                const float* __restrict__ residual,
                                float* __restrict__ outExt,
                                int toHalf, long long total)
{
    double cntd = (double)total;
    double mu = g_stats[statsBase + 0] / cntd;
    double var = g_stats[statsBase + 1] / cntd - mu * mu;
    float rstd = (float)rsqrt(var + 1e-5);
    float fmu = (float)mu;

    long long n4 = total >> 2;
    long long i = (long long)blockIdx.x * blockDim.x + threadIdx.x;
    long long stride = (long long)gridDim.x * blockDim.x;

    for (long long t = i; t < n4; t += stride) {
        int cg = (int)(t & 31);
        float4 g = ((const float4*)gamma)[cg];
        float4 b = ((const float4*)beta)[cg];
        float4 h = ((const float4*)g_hpre)[t];
        float4 v;
        v.x = fmaxf((h.x - fmu) * rstd * g.x + b.x, 0.f);
        v.y = fmaxf((h.y - fmu) * rstd * g.y + b.y, 0.f);
        v.z = fmaxf((h.z - fmu) * rstd * g.z + b.z, 0.f);
        v.w = fmaxf((h.w - fmu) * rstd * g.w + b.w, 0.f);
        if (toHalf) {
            __half2 h0 = __floats2half2_rn(v.x, v.y);
            __half2 h1 = __floats2half2_rn(v.z, v.w);
            uint2 u;
            u.x = *reinterpret_cast<uint32_t*>(&h0);
            u.y = *reinterpret_cast<uint32_t*>(&h1);
            ((uint2*)g_h1h)[t] = u;
        } else {
            float4 r = ((const float4*)residual)[t];
            v.x += r.x; v.y += r.y; v.z += r.z; v.w += r.w;
            ((float4*)outExt)[t] = v;
        }
    }
}

// ---------------------------------------------------------------------------
extern "C" void kernel_launch(void* const* d_in, const int* in_sizes, int n_in,
                              void* d_out, int out_size)
{
    const float* x   = (const float*)d_in[0];
    const int*   ei  = (const int*)d_in[1];   // int32
    const float* Wl1 = (const float*)d_in[2];
    const float* bl1 = (const float*)d_in[3];
    const float* Wr1 = (const float*)d_in[4];
    const float* g1  = (const float*)d_in[5];
    const float* b1  = (const float*)d_in[6];
    const float* Wl2 = (const float*)d_in[7];
    const float* bl2 = (const float*)d_in[8];
    const float* Wr2 = (const float*)d_in[9];
    const float* g2  = (const float*)d_in[10];
    const float* b2  = (const float*)d_in[11];

    int E = in_sizes[1] / 2;
    int nrows = in_sizes[0] / CC;
    long long total = (long long)nrows * CC;

    const int* src = ei;
    const int* dst = ei + E;

    int eBlocks    = (E + 255) / 256;
    int aggBlocks  = (nrows + 7) / 8;
    int gemmBlocks = (nrows + 127) / 128;
    int lnBlocks   = (int)((total / 4 + 255) / 256);
    int scanBlocks = (nrows + SCAN_BLK - 1) / SCAN_BLK;

    // ---- CSR build + x->half ----
    zero_misc_kernel<<<256, 256>>>(nrows);
    x2h_kernel<<<1024, 256>>>(x, total / 4);
    hist_kernel<<<eBlocks, 256>>>(dst, E, nrows);
    scan1_kernel<<<scanBlocks, SCAN_BLK>>>(nrows);
    scan2_kernel<<<1, SCAN_BLK>>>(scanBlocks, nrows);
    scan3_kernel<<<scanBlocks, SCAN_BLK>>>(nrows);
    fill_kernel<<<eBlocks, 256>>>(src, dst, E, nrows);

    // ---- Layer 1 ----
    agg_kernel<<<aggBlocks, 256>>>(nrows, 0);
    gemm_ln_kernel<<<gemmBlocks, 256>>>(x, Wl1, Wr1, bl1, 0, nrows, 0);
    ln_apply_kernel<<<lnBlocks, 256>>>(g1, b1, 0, nullptr, nullptr, 1, total);

    // ---- Layer 2 ----
    agg_kernel<<<aggBlocks, 256>>>(nrows, 1);
    gemm_ln_kernel<<<gemmBlocks, 256>>>(x, Wl2, Wr2, bl2, 2, nrows, 1);
    ln_apply_kernel<<<lnBlocks, 256>>>(g2, b2, 2, x, (float*)d_out, 0, total);
}

// round 10
// speedup vs baseline: 4.1624x; 1.0218x over previous
#include <cuda_runtime.h>
#include <cuda_fp16.h>
#include <cstdint>

// ============================================================================
// GCN SAGE + graph-LayerNorm + residual.
// R10: all fp16 intermediates (agg, hpre, h1, xh) — halves inter-kernel
// traffic; agg unroll x4; A-side tf32 cvt removed (fp16 exact in tf32).
// ============================================================================

#define NN 100000
#define CC 128
#define EMAX 1600000
#define SCAN_BLK 1024

__device__ __half g_aggh[NN * CC];    // aggregated features (fp16)
__device__ __half g_xh[NN * CC];      // x in fp16
__device__ __half g_h1h[NN * CC];     // h1 in fp16
__device__ __half g_hpreh[NN * CC];   // pre-LN buffer (fp16)
__device__ double g_stats[4];
__device__ int    g_deg[NN];
__device__ int    g_off[NN + 1];
__device__ int    g_pos[NN];
__device__ int    g_eidx[EMAX];
__device__ int    g_bsum[SCAN_BLK];

// ---------------------------------------------------------------------------
// Init: zero deg/stats + convert x -> fp16
// ---------------------------------------------------------------------------
__global__ void init_kernel(const float* __restrict__ x, long long n4, int nrows) {
    long long i = (long long)blockIdx.x * blockDim.x + threadIdx.x;
    long long stride = (long long)gridDim.x * blockDim.x;
    for (long long t = i; t < n4; t += stride) {
        float4 v = ((const float4*)x)[t];
        __half2 h0 = __floats2half2_rn(v.x, v.y);
        __half2 h1 = __floats2half2_rn(v.z, v.w);
        uint2 u;
        u.x = *reinterpret_cast<uint32_t*>(&h0);
        u.y = *reinterpret_cast<uint32_t*>(&h1);
        ((uint2*)g_xh)[t] = u;
    }
    for (long long t = i; t < nrows; t += stride) g_deg[t] = 0;
    if (i < 4) g_stats[i] = 0.0;
}

__global__ void hist_kernel(const int* __restrict__ dst, int E, int nrows) {
    int e = blockIdx.x * blockDim.x + threadIdx.x;
    if (e >= E) return;
    int d = dst[e];
    if ((unsigned)d < (unsigned)nrows) atomicAdd(&g_deg[d], 1);
}

__global__ __launch_bounds__(SCAN_BLK) void scan1_kernel(int nrows) {
    __shared__ int sm[SCAN_BLK];
    int t = threadIdx.x;
    int i = blockIdx.x * SCAN_BLK + t;
    int v = (i < nrows) ? g_deg[i] : 0;
    sm[t] = v;
    __syncthreads();
    for (int off = 1; off < SCAN_BLK; off <<= 1) {
        int u = (t >= off) ? sm[t - off] : 0;
        __syncthreads();
        sm[t] += u;
        __syncthreads();
    }
    if (i < nrows) {
        g_off[i] = sm[t] - v;
        g_pos[i] = 0;
    }
    if (t == SCAN_BLK - 1) g_bsum[blockIdx.x] = sm[t];
}

__global__ __launch_bounds__(SCAN_BLK) void scan2_kernel(int nblocks, int nrows) {
    __shared__ int sm[SCAN_BLK];
    int t = threadIdx.x;
    int v = (t < nblocks) ? g_bsum[t] : 0;
    sm[t] = v;
    __syncthreads();
    for (int off = 1; off < SCAN_BLK; off <<= 1) {
        int u = (t >= off) ? sm[t - off] : 0;
        __syncthreads();
        sm[t] += u;
        __syncthreads();
    }
    if (t < nblocks) g_bsum[t] = sm[t] - v;
    if (t == SCAN_BLK - 1) g_off[nrows] = sm[t];
}

__global__ __launch_bounds__(SCAN_BLK) void scan3_kernel(int nrows) {
    int i = blockIdx.x * SCAN_BLK + threadIdx.x;
    if (i < nrows && blockIdx.x > 0) g_off[i] += g_bsum[blockIdx.x];
}

__global__ void fill_kernel(const int* __restrict__ src,
                            const int* __restrict__ dst, int E, int nrows) {
    int e = blockIdx.x * blockDim.x + threadIdx.x;
    if (e >= E) return;
    int d = dst[e];
    int s = src[e];
    if ((unsigned)d >= (unsigned)nrows || (unsigned)s >= (unsigned)nrows) return;
    int p = atomicAdd(&g_pos[d], 1);
    g_eidx[g_off[d] + p] = s;
}

// ---------------------------------------------------------------------------
// Gather aggregation (fp16 in/out), unroll x4 for MLP.
// One warp per dst node; lane owns channels [lane*4, +4).
// ---------------------------------------------------------------------------
__global__ __launch_bounds__(256) void agg_kernel(int nrows, int useH1) {
    int w = (int)(((long long)blockIdx.x * blockDim.x + threadIdx.x) >> 5);
    if (w >= nrows) return;
    int lane = threadIdx.x & 31;
    const __half* __restrict__ h = useH1 ? g_h1h : g_xh;
    const __half* base = h + (size_t)lane * 4;

    int beg = g_off[w];
    int end = g_off[w + 1];
    float4 acc = make_float4(0.f, 0.f, 0.f, 0.f);

    int i = beg;
    for (; i + 4 <= end; i += 4) {
        uint2 r0 = *(const uint2*)(base + (size_t)g_eidx[i + 0] * CC);
        uint2 r1 = *(const uint2*)(base + (size_t)g_eidx[i + 1] * CC);
        uint2 r2 = *(const uint2*)(base + (size_t)g_eidx[i + 2] * CC);
        uint2 r3 = *(const uint2*)(base + (size_t)g_eidx[i + 3] * CC);
        float2 a0 = __half22float2(*reinterpret_cast<__half2*>(&r0.x));
        float2 a1 = __half22float2(*reinterpret_cast<__half2*>(&r0.y));
        float2 b0 = __half22float2(*reinterpret_cast<__half2*>(&r1.x));
        float2 b1 = __half22float2(*reinterpret_cast<__half2*>(&r1.y));
        float2 c0 = __half22float2(*reinterpret_cast<__half2*>(&r2.x));
        float2 c1 = __half22float2(*reinterpret_cast<__half2*>(&r2.y));
        float2 d0 = __half22float2(*reinterpret_cast<__half2*>(&r3.x));
        float2 d1 = __half22float2(*reinterpret_cast<__half2*>(&r3.y));
        acc.x += (a0.x + b0.x) + (c0.x + d0.x);
        acc.y += (a0.y + b0.y) + (c0.y + d0.y);
        acc.z += (a1.x + b1.x) + (c1.x + d1.x);
        acc.w += (a1.y + b1.y) + (c1.y + d1.y);
    }
    for (; i < end; ++i) {
        uint2 r0 = *(const uint2*)(base + (size_t)g_eidx[i] * CC);
        float2 a0 = __half22float2(*reinterpret_cast<__half2*>(&r0.x));
        float2 a1 = __half22float2(*reinterpret_cast<__half2*>(&r0.y));
        acc.x += a0.x; acc.y += a0.y; acc.z += a1.x; acc.w += a1.y;
    }

    float inv = 1.0f / fmaxf((float)(end - beg), 1.0f);
    __half2 o0 = __floats2half2_rn(acc.x * inv, acc.y * inv);
    __half2 o1 = __floats2half2_rn(acc.z * inv, acc.w * inv);
    uint2 u;
    u.x = *reinterpret_cast<uint32_t*>(&o0);
    u.y = *reinterpret_cast<uint32_t*>(&o1);
    ((uint2*)(g_aggh + (size_t)w * CC))[lane] = u;
}

// ---------------------------------------------------------------------------
// TF32 tensor-core fused dual GEMM + LN stats, double-buffered smem.
// A operands all fp16 (exact in tf32, no cvt); W cvt.rna to tf32.
// ---------------------------------------------------------------------------
__device__ __forceinline__ uint32_t f2tf32(float x) {
    uint32_t r;
    asm("cvt.rna.tf32.f32 %0, %1;" : "=r"(r) : "f"(x));
    return r;
}
__device__ __forceinline__ float tf32f(float x) {
    return __uint_as_float(f2tf32(x));
}

__device__ __forceinline__ void mma_tf32(float& d0, float& d1, float& d2, float& d3,
                                         uint32_t a0, uint32_t a1, uint32_t a2, uint32_t a3,
                                         uint32_t b0, uint32_t b1) {
    asm volatile(
        "mma.sync.aligned.m16n8k8.row.col.f32.tf32.tf32.f32 "
        "{%0,%1,%2,%3}, {%4,%5,%6,%7}, {%8,%9}, {%0,%1,%2,%3};"
        : "+f"(d0), "+f"(d1), "+f"(d2), "+f"(d3)
        : "r"(a0), "r"(a1), "r"(a2), "r"(a3), "r"(b0), "r"(b1));
}

#define LDP 136
#define NTILES 16   // 2 phases x 8 K-tiles (BK=16, K=128 each)

__global__ __launch_bounds__(256) void gemm_ln_kernel(
    const float* __restrict__ W0, const float* __restrict__ W1,
    const float* __restrict__ bias,
    int statsBase, int nrows, int useH1)
{
    __shared__ float As[2][16][LDP];
    __shared__ float Ws[2][16][LDP];
    __shared__ double red[256];

    int tid = threadIdx.x;
    int lane = tid & 31;
    int wid = tid >> 5;
    int wm = (wid & 3) * 32;
    int wn = (wid >> 2) * 64;
    int g = lane >> 2;
    int c = lane & 3;
    int row0 = blockIdx.x * 128;

    const __half* __restrict__ A1h = useH1 ? g_h1h : g_xh;

    float acc[2][8][4];
#pragma unroll
    for (int mt = 0; mt < 2; mt++)
#pragma unroll
        for (int nt = 0; nt < 8; nt++)
#pragma unroll
            for (int q = 0; q < 4; q++) acc[mt][nt][q] = 0.f;

    float4 va[2], wv[2];

    auto load_tile = [&](int t) {
        int phase = t >> 3;
        int k0 = (t & 7) * 16;
        const float* W = phase ? W1 : W0;
        const __half* Ah = phase ? A1h : g_aggh;
#pragma unroll
        for (int j = 0; j < 2; ++j) {
            int idx = tid + j * 256;
            int m = idx >> 2;
            int kq = (idx & 3) * 4;
            int gr = row0 + m;
            float4 v = make_float4(0.f, 0.f, 0.f, 0.f);
            if (gr < nrows) {
                uint2 hv = *(const uint2*)(Ah + (size_t)gr * 128 + k0 + kq);
                float2 f0 = __half22float2(*reinterpret_cast<__half2*>(&hv.x));
                float2 f1 = __half22float2(*reinterpret_cast<__half2*>(&hv.y));
                v = make_float4(f0.x, f0.y, f1.x, f1.y);
            }
            va[j] = v;
            int kw = idx >> 5;
            int c4 = idx & 31;
            wv[j] = *(const float4*)(W + (size_t)(k0 + kw) * 128 + c4 * 4);
        }
    };

    auto store_tile = [&](int buf) {
#pragma unroll
        for (int j = 0; j < 2; ++j) {
            int idx = tid + j * 256;
            int m = idx >> 2;
            int kq = (idx & 3) * 4;
            // fp16-sourced values are exact in tf32 -> no cvt needed
            As[buf][kq + 0][m] = va[j].x;
            As[buf][kq + 1][m] = va[j].y;
            As[buf][kq + 2][m] = va[j].z;
            As[buf][kq + 3][m] = va[j].w;
            int kw = idx >> 5;
            int c4 = idx & 31;
            float4 wt;
            wt.x = tf32f(wv[j].x);
            wt.y = tf32f(wv[j].y);
            wt.z = tf32f(wv[j].z);
            wt.w = tf32f(wv[j].w);
            *(float4*)&Ws[buf][kw][c4 * 4] = wt;
        }
    };

    load_tile(0);
    store_tile(0);
    __syncthreads();

    for (int t = 0; t < NTILES; ++t) {
        int buf = t & 1;
        if (t < NTILES - 1) load_tile(t + 1);
#pragma unroll
        for (int ks = 0; ks < 16; ks += 8) {
            uint32_t af[2][4];
#pragma unroll
            for (int mt = 0; mt < 2; mt++) {
                int r = wm + mt * 16 + g;
                af[mt][0] = __float_as_uint(As[buf][ks + c][r]);
                af[mt][1] = __float_as_uint(As[buf][ks + c][r + 8]);
                af[mt][2] = __float_as_uint(As[buf][ks + c + 4][r]);
                af[mt][3] = __float_as_uint(As[buf][ks + c + 4][r + 8]);
            }
            uint32_t bf[8][2];
#pragma unroll
            for (int nt = 0; nt < 8; nt++) {
                int n = wn + nt * 8 + g;
                bf[nt][0] = __float_as_uint(Ws[buf][ks + c][n]);
                bf[nt][1] = __float_as_uint(Ws[buf][ks + c + 4][n]);
            }
#pragma unroll
            for (int mt = 0; mt < 2; mt++)
#pragma unroll
                for (int nt = 0; nt < 8; nt++)
                    mma_tf32(acc[mt][nt][0], acc[mt][nt][1],
                             acc[mt][nt][2], acc[mt][nt][3],
                             af[mt][0], af[mt][1], af[mt][2], af[mt][3],
                             bf[nt][0], bf[nt][1]);
        }
        if (t < NTILES - 1) store_tile(buf ^ 1);
        __syncthreads();
    }

    // Epilogue: bias + fp16 store + LN stats (fp32 accs -> double reduce)
    float s = 0.f, sq = 0.f;
#pragma unroll
    for (int mt = 0; mt < 2; mt++) {
        int r0g = row0 + wm + mt * 16 + g;
#pragma unroll
        for (int nt = 0; nt < 8; nt++) {
            int col = wn + nt * 8 + 2 * c;
            float2 bj = *(const float2*)&bias[col];
            float v0 = acc[mt][nt][0] + bj.x;
            float v1 = acc[mt][nt][1] + bj.y;
            float v2 = acc[mt][nt][2] + bj.x;
            float v3 = acc[mt][nt][3] + bj.y;
            if (r0g < nrows) {
                __half2 hv = __floats2half2_rn(v0, v1);
                *(__half2*)&g_hpreh[(size_t)r0g * 128 + col] = hv;
                s += v0 + v1;
                sq += v0 * v0 + v1 * v1;
            }
            if (r0g + 8 < nrows) {
                __half2 hv = __floats2half2_rn(v2, v3);
                *(__half2*)&g_hpreh[(size_t)(r0g + 8) * 128 + col] = hv;
                s += v2 + v3;
                sq += v2 * v2 + v3 * v3;
            }
        }
    }

    __syncthreads();
    red[tid] = (double)s;
    __syncthreads();
    for (int off = 128; off; off >>= 1) {
        if (tid < off) red[tid] += red[tid + off];
        __syncthreads();
    }
    if (tid == 0) atomicAdd(&g_stats[statsBase + 0], red[0]);
    __syncthreads();
    red[tid] = (double)sq;
    __syncthreads();
    for (int off = 128; off; off >>= 1) {
        if (tid < off) red[tid] += red[tid + off];
        __syncthreads();
    }
    if (tid == 0) atomicAdd(&g_stats[statsBase + 1], red[0]);
}

// ---------------------------------------------------------------------------
// LN apply + ReLU. toHalf: write g_h1h (fp16). Else: fp32 out + residual.
// Each thread handles 4 halves (uint2).
// ---------------------------------------------------------------------------
__global__ void ln_apply_kernel(const float* __restrict__ gamma,
                                const float* __restrict__ beta,
                                int statsBase,
                                const float* __restrict__ residual,
                                float* __restrict__ outExt,
                                int toHalf, long long total)
{
    double cntd = (double)total;
    double mu = g_stats[statsBase + 0] / cntd;
    double var = g_stats[statsBase + 1] / cntd - mu * mu;
    float rstd = (float)rsqrt(var + 1e-5);
    float fmu = (float)mu;

    long long n4 = total >> 2;
    long long i = (long long)blockIdx.x * blockDim.x + threadIdx.x;
    long long stride = (long long)gridDim.x * blockDim.x;

    for (long long t = i; t < n4; t += stride) {
        int cg = (int)(t & 31);
        float4 g = ((const float4*)gamma)[cg];
        float4 b = ((const float4*)beta)[cg];
        uint2 hu = ((const uint2*)g_hpreh)[t];
        float2 h0 = __half22float2(*reinterpret_cast<__half2*>(&hu.x));
        float2 h1 = __half22float2(*reinterpret_cast<__half2*>(&hu.y));
        float4 v;
        v.x = fmaxf((h0.x - fmu) * rstd * g.x + b.x, 0.f);
        v.y = fmaxf((h0.y - fmu) * rstd * g.y + b.y, 0.f);
        v.z = fmaxf((h1.x - fmu) * rstd * g.z + b.z, 0.f);
        v.w = fmaxf((h1.y - fmu) * rstd * g.w + b.w, 0.f);
        if (toHalf) {
            __half2 o0 = __floats2half2_rn(v.x, v.y);
            __half2 o1 = __floats2half2_rn(v.z, v.w);
            uint2 u;
            u.x = *reinterpret_cast<uint32_t*>(&o0);
            u.y = *reinterpret_cast<uint32_t*>(&o1);
            ((uint2*)g_h1h)[t] = u;
        } else {
            float4 r = ((const float4*)residual)[t];
            v.x += r.x; v.y += r.y; v.z += r.z; v.w += r.w;
            ((float4*)outExt)[t] = v;
        }
    }
}

// ---------------------------------------------------------------------------
extern "C" void kernel_launch(void* const* d_in, const int* in_sizes, int n_in,
                              void* d_out, int out_size)
{
    const float* x   = (const float*)d_in[0];
    const int*   ei  = (const int*)d_in[1];   // int32
    const float* Wl1 = (const float*)d_in[2];
    const float* bl1 = (const float*)d_in[3];
    const float* Wr1 = (const float*)d_in[4];
    const float* g1  = (const float*)d_in[5];
    const float* b1  = (const float*)d_in[6];
    const float* Wl2 = (const float*)d_in[7];
    const float* bl2 = (const float*)d_in[8];
    const float* Wr2 = (const float*)d_in[9];
    const float* g2  = (const float*)d_in[10];
    const float* b2  = (const float*)d_in[11];

    int E = in_sizes[1] / 2;
    int nrows = in_sizes[0] / CC;
    long long total = (long long)nrows * CC;

    const int* src = ei;
    const int* dst = ei + E;

    int eBlocks    = (E + 255) / 256;
    int aggBlocks  = (nrows + 7) / 8;
    int gemmBlocks = (nrows + 127) / 128;
    int lnBlocks   = (int)((total / 4 + 255) / 256);
    int scanBlocks = (nrows + SCAN_BLK - 1) / SCAN_BLK;

    // ---- CSR build + x->half ----
    init_kernel<<<1024, 256>>>(x, total / 4, nrows);
    hist_kernel<<<eBlocks, 256>>>(dst, E, nrows);
    scan1_kernel<<<scanBlocks, SCAN_BLK>>>(nrows);
    scan2_kernel<<<1, SCAN_BLK>>>(scanBlocks, nrows);
    scan3_kernel<<<scanBlocks, SCAN_BLK>>>(nrows);
    fill_kernel<<<eBlocks, 256>>>(src, dst, E, nrows);

    // ---- Layer 1 ----
    agg_kernel<<<aggBlocks, 256>>>(nrows, 0);
    gemm_ln_kernel<<<gemmBlocks, 256>>>(Wl1, Wr1, bl1, 0, nrows, 0);
    ln_apply_kernel<<<lnBlocks, 256>>>(g1, b1, 0, nullptr, nullptr, 1, total);

    // ---- Layer 2 ----
    agg_kernel<<<aggBlocks, 256>>>(nrows, 1);
    gemm_ln_kernel<<<gemmBlocks, 256>>>(Wl2, Wr2, bl2, 2, nrows, 1);
    ln_apply_kernel<<<lnBlocks, 256>>>(g2, b2, 2, x, (float*)d_out, 0, total);
}

// round 11
// speedup vs baseline: 4.1659x; 1.0009x over previous
#include <cuda_runtime.h>
#include <cuda_fp16.h>
#include <cstdint>

// ============================================================================
// GCN SAGE + graph-LayerNorm + residual.
// R10: all fp16 intermediates (agg, hpre, h1, xh) — halves inter-kernel
// traffic; agg unroll x4; A-side tf32 cvt removed (fp16 exact in tf32).
// ============================================================================

#define NN 100000
#define CC 128
#define EMAX 1600000
#define SCAN_BLK 1024

__device__ __half g_aggh[NN * CC];    // aggregated features (fp16)
__device__ __half g_xh[NN * CC];      // x in fp16
__device__ __half g_h1h[NN * CC];     // h1 in fp16
__device__ __half g_hpreh[NN * CC];   // pre-LN buffer (fp16)
__device__ double g_stats[4];
__device__ int    g_deg[NN];
__device__ int    g_off[NN + 1];
__device__ int    g_pos[NN];
__device__ int    g_eidx[EMAX];
__device__ int    g_bsum[SCAN_BLK];

// ---------------------------------------------------------------------------
// Init: zero deg/stats + convert x -> fp16
// ---------------------------------------------------------------------------
__global__ void init_kernel(const float* __restrict__ x, long long n4, int nrows) {
    long long i = (long long)blockIdx.x * blockDim.x + threadIdx.x;
    long long stride = (long long)gridDim.x * blockDim.x;
    for (long long t = i; t < n4; t += stride) {
        float4 v = ((const float4*)x)[t];
        __half2 h0 = __floats2half2_rn(v.x, v.y);
        __half2 h1 = __floats2half2_rn(v.z, v.w);
        uint2 u;
        u.x = *reinterpret_cast<uint32_t*>(&h0);
        u.y = *reinterpret_cast<uint32_t*>(&h1);
        ((uint2*)g_xh)[t] = u;
    }
    for (long long t = i; t < nrows; t += stride) g_deg[t] = 0;
    if (i < 4) g_stats[i] = 0.0;
}

__global__ void hist_kernel(const int* __restrict__ dst, int E, int nrows) {
    int e = blockIdx.x * blockDim.x + threadIdx.x;
    if (e >= E) return;
    int d = dst[e];
    if ((unsigned)d < (unsigned)nrows) atomicAdd(&g_deg[d], 1);
}

__global__ __launch_bounds__(SCAN_BLK) void scan1_kernel(int nrows) {
    __shared__ int sm[SCAN_BLK];
    int t = threadIdx.x;
    int i = blockIdx.x * SCAN_BLK + t;
    int v = (i < nrows) ? g_deg[i] : 0;
    sm[t] = v;
    __syncthreads();
    for (int off = 1; off < SCAN_BLK; off <<= 1) {
        int u = (t >= off) ? sm[t - off] : 0;
        __syncthreads();
        sm[t] += u;
        __syncthreads();
    }
    if (i < nrows) {
        g_off[i] = sm[t] - v;
        g_pos[i] = 0;
    }
    if (t == SCAN_BLK - 1) g_bsum[blockIdx.x] = sm[t];
}

__global__ __launch_bounds__(SCAN_BLK) void scan2_kernel(int nblocks, int nrows) {
    __shared__ int sm[SCAN_BLK];
    int t = threadIdx.x;
    int v = (t < nblocks) ? g_bsum[t] : 0;
    sm[t] = v;
    __syncthreads();
    for (int off = 1; off < SCAN_BLK; off <<= 1) {
        int u = (t >= off) ? sm[t - off] : 0;
        __syncthreads();
        sm[t] += u;
        __syncthreads();
    }
    if (t < nblocks) g_bsum[t] = sm[t] - v;
    if (t == SCAN_BLK - 1) g_off[nrows] = sm[t];
}

__global__ __launch_bounds__(SCAN_BLK) void scan3_kernel(int nrows) {
    int i = blockIdx.x * SCAN_BLK + threadIdx.x;
    if (i < nrows && blockIdx.x > 0) g_off[i] += g_bsum[blockIdx.x];
}

__global__ void fill_kernel(const int* __restrict__ src,
                            const int* __restrict__ dst, int E, int nrows) {
    int e = blockIdx.x * blockDim.x + threadIdx.x;
    if (e >= E) return;
    int d = dst[e];
    int s = src[e];
    if ((unsigned)d >= (unsigned)nrows || (unsigned)s >= (unsigned)nrows) return;
    int p = atomicAdd(&g_pos[d], 1);
    g_eidx[g_off[d] + p] = s;
}

// ---------------------------------------------------------------------------
// Gather aggregation (fp16 in/out), unroll x4 for MLP.
// One warp per dst node; lane owns channels [lane*4, +4).
// ---------------------------------------------------------------------------
__global__ __launch_bounds__(256) void agg_kernel(int nrows, int useH1) {
    int w = (int)(((long long)blockIdx.x * blockDim.x + threadIdx.x) >> 5);
    if (w >= nrows) return;
    int lane = threadIdx.x & 31;
    const __half* __restrict__ h = useH1 ? g_h1h : g_xh;
    const __half* base = h + (size_t)lane * 4;

    int beg = g_off[w];
    int end = g_off[w + 1];
    float4 acc = make_float4(0.f, 0.f, 0.f, 0.f);

    int i = beg;
    for (; i + 4 <= end; i += 4) {
        uint2 r0 = *(const uint2*)(base + (size_t)g_eidx[i + 0] * CC);
        uint2 r1 = *(const uint2*)(base + (size_t)g_eidx[i + 1] * CC);
        uint2 r2 = *(const uint2*)(base + (size_t)g_eidx[i + 2] * CC);
        uint2 r3 = *(const uint2*)(base + (size_t)g_eidx[i + 3] * CC);
        float2 a0 = __half22float2(*reinterpret_cast<__half2*>(&r0.x));
        float2 a1 = __half22float2(*reinterpret_cast<__half2*>(&r0.y));
        float2 b0 = __half22float2(*reinterpret_cast<__half2*>(&r1.x));
        float2 b1 = __half22float2(*reinterpret_cast<__half2*>(&r1.y));
        float2 c0 = __half22float2(*reinterpret_cast<__half2*>(&r2.x));
        float2 c1 = __half22float2(*reinterpret_cast<__half2*>(&r2.y));
        float2 d0 = __half22float2(*reinterpret_cast<__half2*>(&r3.x));
        float2 d1 = __half22float2(*reinterpret_cast<__half2*>(&r3.y));
        acc.x += (a0.x + b0.x) + (c0.x + d0.x);
        acc.y += (a0.y + b0.y) + (c0.y + d0.y);
        acc.z += (a1.x + b1.x) + (c1.x + d1.x);
        acc.w += (a1.y + b1.y) + (c1.y + d1.y);
    }
    for (; i < end; ++i) {
        uint2 r0 = *(const uint2*)(base + (size_t)g_eidx[i] * CC);
        float2 a0 = __half22float2(*reinterpret_cast<__half2*>(&r0.x));
        float2 a1 = __half22float2(*reinterpret_cast<__half2*>(&r0.y));
        acc.x += a0.x; acc.y += a0.y; acc.z += a1.x; acc.w += a1.y;
    }

    float inv = 1.0f / fmaxf((float)(end - beg), 1.0f);
    __half2 o0 = __floats2half2_rn(acc.x * inv, acc.y * inv);
    __half2 o1 = __floats2half2_rn(acc.z * inv, acc.w * inv);
    uint2 u;
    u.x = *reinterpret_cast<uint32_t*>(&o0);
    u.y = *reinterpret_cast<uint32_t*>(&o1);
    ((uint2*)(g_aggh + (size_t)w * CC))[lane] = u;
}

// ---------------------------------------------------------------------------
// TF32 tensor-core fused dual GEMM + LN stats, double-buffered smem.
// A operands all fp16 (exact in tf32, no cvt); W cvt.rna to tf32.
// ---------------------------------------------------------------------------
__device__ __forceinline__ uint32_t f2tf32(float x) {
    uint32_t r;
    asm("cvt.rna.tf32.f32 %0, %1;" : "=r"(r) : "f"(x));
    return r;
}
__device__ __forceinline__ float tf32f(float x) {
    return __uint_as_float(f2tf32(x));
}

__device__ __forceinline__ void mma_tf32(float& d0, float& d1, float& d2, float& d3,
                                         uint32_t a0, uint32_t a1, uint32_t a2, uint32_t a3,
                                         uint32_t b0, uint32_t b1) {
    asm volatile(
        "mma.sync.aligned.m16n8k8.row.col.f32.tf32.tf32.f32 "
        "{%0,%1,%2,%3}, {%4,%5,%6,%7}, {%8,%9}, {%0,%1,%2,%3};"
        : "+f"(d0), "+f"(d1), "+f"(d2), "+f"(d3)
        : "r"(a0), "r"(a1), "r"(a2), "r"(a3), "r"(b0), "r"(b1));
}

#define LDP 136
#define NTILES 16   // 2 phases x 8 K-tiles (BK=16, K=128 each)

__global__ __launch_bounds__(256) void gemm_ln_kernel(
    const float* __restrict__ W0, const float* __restrict__ W1,
    const float* __restrict__ bias,
    int statsBase, int nrows, int useH1)
{
    __shared__ float As[2][16][LDP];
    __shared__ float Ws[2][16][LDP];
    __shared__ double red[256];

    int tid = threadIdx.x;
    int lane = tid & 31;
    int wid = tid >> 5;
    int wm = (wid & 3) * 32;
    int wn = (wid >> 2) * 64;
    int g = lane >> 2;
    int c = lane & 3;
    int row0 = blockIdx.x * 128;

    const __half* __restrict__ A1h = useH1 ? g_h1h : g_xh;

    float acc[2][8][4];
#pragma unroll
    for (int mt = 0; mt < 2; mt++)
#pragma unroll
        for (int nt = 0; nt < 8; nt++)
#pragma unroll
            for (int q = 0; q < 4; q++) acc[mt][nt][q] = 0.f;

    float4 va[2], wv[2];

    auto load_tile = [&](int t) {
        int phase = t >> 3;
        int k0 = (t & 7) * 16;
        const float* W = phase ? W1 : W0;
        const __half* Ah = phase ? A1h : g_aggh;
#pragma unroll
        for (int j = 0; j < 2; ++j) {
            int idx = tid + j * 256;
            int m = idx >> 2;
            int kq = (idx & 3) * 4;
            int gr = row0 + m;
            float4 v = make_float4(0.f, 0.f, 0.f, 0.f);
            if (gr < nrows) {
                uint2 hv = *(const uint2*)(Ah + (size_t)gr * 128 + k0 + kq);
                float2 f0 = __half22float2(*reinterpret_cast<__half2*>(&hv.x));
                float2 f1 = __half22float2(*reinterpret_cast<__half2*>(&hv.y));
                v = make_float4(f0.x, f0.y, f1.x, f1.y);
            }
            va[j] = v;
            int kw = idx >> 5;
            int c4 = idx & 31;
            wv[j] = *(const float4*)(W + (size_t)(k0 + kw) * 128 + c4 * 4);
        }
    };

    auto store_tile = [&](int buf) {
#pragma unroll
        for (int j = 0; j < 2; ++j) {
            int idx = tid + j * 256;
            int m = idx >> 2;
            int kq = (idx & 3) * 4;
            // fp16-sourced values are exact in tf32 -> no cvt needed
            As[buf][kq + 0][m] = va[j].x;
            As[buf][kq + 1][m] = va[j].y;
            As[buf][kq + 2][m] = va[j].z;
            As[buf][kq + 3][m] = va[j].w;
            int kw = idx >> 5;
            int c4 = idx & 31;
            float4 wt;
            wt.x = tf32f(wv[j].x);
            wt.y = tf32f(wv[j].y);
            wt.z = tf32f(wv[j].z);
            wt.w = tf32f(wv[j].w);
            *(float4*)&Ws[buf][kw][c4 * 4] = wt;
        }
    };

    load_tile(0);
    store_tile(0);
    __syncthreads();

    for (int t = 0; t < NTILES; ++t) {
        int buf = t & 1;
        if (t < NTILES - 1) load_tile(t + 1);
#pragma unroll
        for (int ks = 0; ks < 16; ks += 8) {
            uint32_t af[2][4];
#pragma unroll
            for (int mt = 0; mt < 2; mt++) {
                int r = wm + mt * 16 + g;
                af[mt][0] = __float_as_uint(As[buf][ks + c][r]);
                af[mt][1] = __float_as_uint(As[buf][ks + c][r + 8]);
                af[mt][2] = __float_as_uint(As[buf][ks + c + 4][r]);
                af[mt][3] = __float_as_uint(As[buf][ks + c + 4][r + 8]);
            }
            uint32_t bf[8][2];
#pragma unroll
            for (int nt = 0; nt < 8; nt++) {
                int n = wn + nt * 8 + g;
                bf[nt][0] = __float_as_uint(Ws[buf][ks + c][n]);
                bf[nt][1] = __float_as_uint(Ws[buf][ks + c + 4][n]);
            }
#pragma unroll
            for (int mt = 0; mt < 2; mt++)
#pragma unroll
                for (int nt = 0; nt < 8; nt++)
                    mma_tf32(acc[mt][nt][0], acc[mt][nt][1],
                             acc[mt][nt][2], acc[mt][nt][3],
                             af[mt][0], af[mt][1], af[mt][2], af[mt][3],
                             bf[nt][0], bf[nt][1]);
        }
        if (t < NTILES - 1) store_tile(buf ^ 1);
        __syncthreads();
    }

    // Epilogue: bias + fp16 store + LN stats (fp32 accs -> double reduce)
    float s = 0.f, sq = 0.f;
#pragma unroll
    for (int mt = 0; mt < 2; mt++) {
        int r0g = row0 + wm + mt * 16 + g;
#pragma unroll
        for (int nt = 0; nt < 8; nt++) {
            int col = wn + nt * 8 + 2 * c;
            float2 bj = *(const float2*)&bias[col];
            float v0 = acc[mt][nt][0] + bj.x;
            float v1 = acc[mt][nt][1] + bj.y;
            float v2 = acc[mt][nt][2] + bj.x;
            float v3 = acc[mt][nt][3] + bj.y;
            if (r0g < nrows) {
                __half2 hv = __floats2half2_rn(v0, v1);
                *(__half2*)&g_hpreh[(size_t)r0g * 128 + col] = hv;
                s += v0 + v1;
                sq += v0 * v0 + v1 * v1;
            }
            if (r0g + 8 < nrows) {
                __half2 hv = __floats2half2_rn(v2, v3);
                *(__half2*)&g_hpreh[(size_t)(r0g + 8) * 128 + col] = hv;
                s += v2 + v3;
                sq += v2 * v2 + v3 * v3;
            }
        }
    }

    __syncthreads();
    red[tid] = (double)s;
    __syncthreads();
    for (int off = 128; off; off >>= 1) {
        if (tid < off) red[tid] += red[tid + off];
        __syncthreads();
    }
    if (tid == 0) atomicAdd(&g_stats[statsBase + 0], red[0]);
    __syncthreads();
    red[tid] = (double)sq;
    __syncthreads();
    for (int off = 128; off; off >>= 1) {
        if (tid < off) red[tid] += red[tid + off];
        __syncthreads();
    }
    if (tid == 0) atomicAdd(&g_stats[statsBase + 1], red[0]);
}

// ---------------------------------------------------------------------------
// LN apply + ReLU. toHalf: write g_h1h (fp16). Else: fp32 out + residual.
// Each thread handles 4 halves (uint2).
// ---------------------------------------------------------------------------
__global__ void ln_apply_kernel(const float* __restrict__ gamma,
                                const float* __restrict__ beta,
                                int statsBase,
                                const float* __restrict__ residual,
                                float* __restrict__ outExt,
                                int toHalf, long long total)
{
    double cntd = (double)total;
    double mu = g_stats[statsBase + 0] / cntd;
    double var = g_stats[statsBase + 1] / cntd - mu * mu;
    float rstd = (float)rsqrt(var + 1e-5);
    float fmu = (float)mu;

    long long n4 = total >> 2;
    long long i = (long long)blockIdx.x * blockDim.x + threadIdx.x;
    long long stride = (long long)gridDim.x * blockDim.x;

    for (long long t = i; t < n4; t += stride) {
        int cg = (int)(t & 31);
        float4 g = ((const float4*)gamma)[cg];
        float4 b = ((const float4*)beta)[cg];
        uint2 hu = ((const uint2*)g_hpreh)[t];
        float2 h0 = __half22float2(*reinterpret_cast<__half2*>(&hu.x));
        float2 h1 = __half22float2(*reinterpret_cast<__half2*>(&hu.y));
        float4 v;
        v.x = fmaxf((h0.x - fmu) * rstd * g.x + b.x, 0.f);
        v.y = fmaxf((h0.y - fmu) * rstd * g.y + b.y, 0.f);
        v.z = fmaxf((h1.x - fmu) * rstd * g.z + b.z, 0.f);
        v.w = fmaxf((h1.y - fmu) * rstd * g.w + b.w, 0.f);
        if (toHalf) {
            __half2 o0 = __floats2half2_rn(v.x, v.y);
            __half2 o1 = __floats2half2_rn(v.z, v.w);
            uint2 u;
            u.x = *reinterpret_cast<uint32_t*>(&o0);
            u.y = *reinterpret_cast<uint32_t*>(&o1);
            ((uint2*)g_h1h)[t] = u;
        } else {
            float4 r = ((const float4*)residual)[t];
            v.x += r.x; v.y += r.y; v.z += r.z; v.w += r.w;
            ((float4*)outExt)[t] = v;
        }
    }
}

// ---------------------------------------------------------------------------
extern "C" void kernel_launch(void* const* d_in, const int* in_sizes, int n_in,
                              void* d_out, int out_size)
{
    const float* x   = (const float*)d_in[0];
    const int*   ei  = (const int*)d_in[1];   // int32
    const float* Wl1 = (const float*)d_in[2];
    const float* bl1 = (const float*)d_in[3];
    const float* Wr1 = (const float*)d_in[4];
    const float* g1  = (const float*)d_in[5];
    const float* b1  = (const float*)d_in[6];
    const float* Wl2 = (const float*)d_in[7];
    const float* bl2 = (const float*)d_in[8];
    const float* Wr2 = (const float*)d_in[9];
    const float* g2  = (const float*)d_in[10];
    const float* b2  = (const float*)d_in[11];

    int E = in_sizes[1] / 2;
    int nrows = in_sizes[0] / CC;
    long long total = (long long)nrows * CC;

    const int* src = ei;
    const int* dst = ei + E;

    int eBlocks    = (E + 255) / 256;
    int aggBlocks  = (nrows + 7) / 8;
    int gemmBlocks = (nrows + 127) / 128;
    int lnBlocks   = (int)((total / 4 + 255) / 256);
    int scanBlocks = (nrows + SCAN_BLK - 1) / SCAN_BLK;

    // ---- CSR build + x->half ----
    init_kernel<<<1024, 256>>>(x, total / 4, nrows);
    hist_kernel<<<eBlocks, 256>>>(dst, E, nrows);
    scan1_kernel<<<scanBlocks, SCAN_BLK>>>(nrows);
    scan2_kernel<<<1, SCAN_BLK>>>(scanBlocks, nrows);
    scan3_kernel<<<scanBlocks, SCAN_BLK>>>(nrows);
    fill_kernel<<<eBlocks, 256>>>(src, dst, E, nrows);

    // ---- Layer 1 ----
    agg_kernel<<<aggBlocks, 256>>>(nrows, 0);
    gemm_ln_kernel<<<gemmBlocks, 256>>>(Wl1, Wr1, bl1, 0, nrows, 0);
    ln_apply_kernel<<<lnBlocks, 256>>>(g1, b1, 0, nullptr, nullptr, 1, total);

    // ---- Layer 2 ----
    agg_kernel<<<aggBlocks, 256>>>(nrows, 1);
    gemm_ln_kernel<<<gemmBlocks, 256>>>(Wl2, Wr2, bl2, 2, nrows, 1);
    ln_apply_kernel<<<lnBlocks, 256>>>(g2, b2, 2, x, (float*)d_out, 0, total);
}

// round 14
// speedup vs baseline: 4.1913x; 1.0061x over previous
#include <cuda_runtime.h>
#include <cuda_fp16.h>
#include <cstdint>

// ============================================================================
// GCN SAGE + graph-LayerNorm + residual.
// R14 = R12 resubmitted unchanged (two consecutive GB300 container-acquisition
// failures; kernel never executed — no evidence to update on).
// Ticket-based CSR fill (no fill atomics); layer-1 LN+ReLU fused into
// layer-2 consumers (agg + GEMM A-load) — ln_apply pass for layer 1 removed.
// ============================================================================

#define NN 100000
#define CC 128
#define EMAX 1600000
#define SCAN_BLK 1024

__device__ __half g_aggh[NN * CC];    // aggregated features (fp16)
__device__ __half g_xh[NN * CC];      // x in fp16
__device__ __half g_hpreh[NN * CC];   // pre-LN buffer (fp16), both layers
__device__ double g_stats[4];
__device__ float  g_mu0, g_rstd0;     // finalized layer-1 LN scalars
__device__ int    g_deg[NN];
__device__ int    g_off[NN + 1];
__device__ int    g_tick[EMAX];       // per-edge slot ticket
__device__ int    g_eidx[EMAX];
__device__ int    g_bsum[SCAN_BLK];

// ---------------------------------------------------------------------------
__global__ void init_kernel(const float* __restrict__ x, long long n4, int nrows) {
    long long i = (long long)blockIdx.x * blockDim.x + threadIdx.x;
    long long stride = (long long)gridDim.x * blockDim.x;
    for (long long t = i; t < n4; t += stride) {
        float4 v = ((const float4*)x)[t];
        __half2 h0 = __floats2half2_rn(v.x, v.y);
        __half2 h1 = __floats2half2_rn(v.z, v.w);
        uint2 u;
        u.x = *reinterpret_cast<uint32_t*>(&h0);
        u.y = *reinterpret_cast<uint32_t*>(&h1);
        ((uint2*)g_xh)[t] = u;
    }
    for (long long t = i; t < nrows; t += stride) g_deg[t] = 0;
    if (i < 4) g_stats[i] = 0.0;
}

// hist + ticket: ticket = this edge's slot within its dst bucket.
__global__ void hist_kernel(const int* __restrict__ dst, int E, int nrows) {
    int e = blockIdx.x * blockDim.x + threadIdx.x;
    if (e >= E) return;
    int d = dst[e];
    if ((unsigned)d < (unsigned)nrows)
        g_tick[e] = atomicAdd(&g_deg[d], 1);
}

__global__ __launch_bounds__(SCAN_BLK) void scan1_kernel(int nrows) {
    __shared__ int sm[SCAN_BLK];
    int t = threadIdx.x;
    int i = blockIdx.x * SCAN_BLK + t;
    int v = (i < nrows) ? g_deg[i] : 0;
    sm[t] = v;
    __syncthreads();
    for (int off = 1; off < SCAN_BLK; off <<= 1) {
        int u = (t >= off) ? sm[t - off] : 0;
        __syncthreads();
        sm[t] += u;
        __syncthreads();
    }
    if (i < nrows) g_off[i] = sm[t] - v;
    if (t == SCAN_BLK - 1) g_bsum[blockIdx.x] = sm[t];
}

__global__ __launch_bounds__(SCAN_BLK) void scan2_kernel(int nblocks, int nrows) {
    __shared__ int sm[SCAN_BLK];
    int t = threadIdx.x;
    int v = (t < nblocks) ? g_bsum[t] : 0;
    sm[t] = v;
    __syncthreads();
    for (int off = 1; off < SCAN_BLK; off <<= 1) {
        int u = (t >= off) ? sm[t - off] : 0;
        __syncthreads();
        sm[t] += u;
        __syncthreads();
    }
    if (t < nblocks) g_bsum[t] = sm[t] - v;
    if (t == SCAN_BLK - 1) g_off[nrows] = sm[t];
}

__global__ __launch_bounds__(SCAN_BLK) void scan3_kernel(int nrows) {
    int i = blockIdx.x * SCAN_BLK + threadIdx.x;
    if (i < nrows && blockIdx.x > 0) g_off[i] += g_bsum[blockIdx.x];
}

// Atomic-free fill using tickets.
__global__ void fill_kernel(const int* __restrict__ src,
                            const int* __restrict__ dst, int E, int nrows) {
    int e = blockIdx.x * blockDim.x + threadIdx.x;
    if (e >= E) return;
    int d = dst[e];
    int s = src[e];
    if ((unsigned)d >= (unsigned)nrows || (unsigned)s >= (unsigned)nrows) return;
    g_eidx[g_off[d] + g_tick[e]] = s;
}

// Finalize layer-1 LN scalars (after layer-1 GEMM stats complete).
__global__ void finalize_kernel(long long total) {
    if (threadIdx.x == 0) {
        double mu = g_stats[0] / (double)total;
        double var = g_stats[1] / (double)total - mu * mu;
        g_mu0 = (float)mu;
        g_rstd0 = (float)rsqrt(var + 1e-5);
    }
}

// ---------------------------------------------------------------------------
// Gather aggregation. layer=0: plain gather from g_xh.
// layer=1: gather from g_hpreh, applying LN1 affine + ReLU on the fly.
// One warp per dst node; lane owns channels [lane*4, +4).
// ---------------------------------------------------------------------------
__global__ __launch_bounds__(256) void agg_kernel(int nrows, int layer,
                                                  const float* __restrict__ gamma,
                                                  const float* __restrict__ beta) {
    int w = (int)(((long long)blockIdx.x * blockDim.x + threadIdx.x) >> 5);
    if (w >= nrows) return;
    int lane = threadIdx.x & 31;
    const __half* __restrict__ h = layer ? g_hpreh : g_xh;
    const __half* base = h + (size_t)lane * 4;

    float4 ga = make_float4(0.f, 0.f, 0.f, 0.f);
    float4 be = make_float4(0.f, 0.f, 0.f, 0.f);
    float mu = 0.f, rstd = 0.f;
    if (layer) {
        ga = *(const float4*)&gamma[lane * 4];
        be = *(const float4*)&beta[lane * 4];
        mu = g_mu0;
        rstd = g_rstd0;
        // pre-fold: relu((h-mu)*rstd*g + b) = relu(h*(rstd*g) + (b - mu*rstd*g))
        ga.x *= rstd; ga.y *= rstd; ga.z *= rstd; ga.w *= rstd;
        be.x -= mu * ga.x; be.y -= mu * ga.y; be.z -= mu * ga.z; be.w -= mu * ga.w;
    }

    int beg = g_off[w];
    int end = g_off[w + 1];
    float4 acc = make_float4(0.f, 0.f, 0.f, 0.f);

#define LOADROW(rr, f0, f1)                                             \
    float2 f0 = __half22float2(*reinterpret_cast<__half2*>(&rr.x));     \
    float2 f1 = __half22float2(*reinterpret_cast<__half2*>(&rr.y));

#define APPLYLN(f0, f1)                                                 \
    if (layer) {                                                        \
        f0.x = fmaxf(f0.x * ga.x + be.x, 0.f);                          \
        f0.y = fmaxf(f0.y * ga.y + be.y, 0.f);                          \
        f1.x = fmaxf(f1.x * ga.z + be.z, 0.f);                          \
        f1.y = fmaxf(f1.y * ga.w + be.w, 0.f);                          \
    }

    int i = beg;
    for (; i + 4 <= end; i += 4) {
        uint2 r0 = *(const uint2*)(base + (size_t)g_eidx[i + 0] * CC);
        uint2 r1 = *(const uint2*)(base + (size_t)g_eidx[i + 1] * CC);
        uint2 r2 = *(const uint2*)(base + (size_t)g_eidx[i + 2] * CC);
        uint2 r3 = *(const uint2*)(base + (size_t)g_eidx[i + 3] * CC);
        LOADROW(r0, a0, a1) LOADROW(r1, b0, b1)
        LOADROW(r2, c0, c1) LOADROW(r3, d0, d1)
        APPLYLN(a0, a1) APPLYLN(b0, b1) APPLYLN(c0, c1) APPLYLN(d0, d1)
        acc.x += (a0.x + b0.x) + (c0.x + d0.x);
        acc.y += (a0.y + b0.y) + (c0.y + d0.y);
        acc.z += (a1.x + b1.x) + (c1.x + d1.x);
        acc.w += (a1.y + b1.y) + (c1.y + d1.y);
    }
    for (; i < end; ++i) {
        uint2 r0 = *(const uint2*)(base + (size_t)g_eidx[i] * CC);
        LOADROW(r0, a0, a1)
        APPLYLN(a0, a1)
        acc.x += a0.x; acc.y += a0.y; acc.z += a1.x; acc.w += a1.y;
    }
#undef LOADROW
#undef APPLYLN

    float inv = 1.0f / fmaxf((float)(end - beg), 1.0f);
    __half2 o0 = __floats2half2_rn(acc.x * inv, acc.y * inv);
    __half2 o1 = __floats2half2_rn(acc.z * inv, acc.w * inv);
    uint2 u;
    u.x = *reinterpret_cast<uint32_t*>(&o0);
    u.y = *reinterpret_cast<uint32_t*>(&o1);
    ((uint2*)(g_aggh + (size_t)w * CC))[lane] = u;
}

// ---------------------------------------------------------------------------
// TF32 tensor-core fused dual GEMM + LN stats, double-buffered smem.
// layer=0: A1 = g_xh (plain). layer=1: A1 = relu(LN1(g_hpreh)) on the fly.
// ---------------------------------------------------------------------------
__device__ __forceinline__ uint32_t f2tf32(float x) {
    uint32_t r;
    asm("cvt.rna.tf32.f32 %0, %1;" : "=r"(r) : "f"(x));
    return r;
}
__device__ __forceinline__ float tf32f(float x) {
    return __uint_as_float(f2tf32(x));
}

__device__ __forceinline__ void mma_tf32(float& d0, float& d1, float& d2, float& d3,
                                         uint32_t a0, uint32_t a1, uint32_t a2, uint32_t a3,
                                         uint32_t b0, uint32_t b1) {
    asm volatile(
        "mma.sync.aligned.m16n8k8.row.col.f32.tf32.tf32.f32 "
        "{%0,%1,%2,%3}, {%4,%5,%6,%7}, {%8,%9}, {%0,%1,%2,%3};"
        : "+f"(d0), "+f"(d1), "+f"(d2), "+f"(d3)
        : "r"(a0), "r"(a1), "r"(a2), "r"(a3), "r"(b0), "r"(b1));
}

#define LDP 136
#define NTILES 16

__global__ __launch_bounds__(256) void gemm_ln_kernel(
    const float* __restrict__ W0, const float* __restrict__ W1,
    const float* __restrict__ bias,
    const float* __restrict__ lnGamma, const float* __restrict__ lnBeta,
    int statsBase, int nrows, int layer)
{
    __shared__ float As[2][16][LDP];
    __shared__ float Ws[2][16][LDP];
    __shared__ double red[256];

    int tid = threadIdx.x;
    int lane = tid & 31;
    int wid = tid >> 5;
    int wm = (wid & 3) * 32;
    int wn = (wid >> 2) * 64;
    int g = lane >> 2;
    int c = lane & 3;
    int row0 = blockIdx.x * 128;

    float mu = 0.f, rstd = 0.f;
    if (layer) { mu = g_mu0; rstd = g_rstd0; }

    float acc[2][8][4];
#pragma unroll
    for (int mt = 0; mt < 2; mt++)
#pragma unroll
        for (int nt = 0; nt < 8; nt++)
#pragma unroll
            for (int q = 0; q < 4; q++) acc[mt][nt][q] = 0.f;

    float4 va[2], wv[2];

    auto load_tile = [&](int t) {
        int phase = t >> 3;
        int k0 = (t & 7) * 16;
        const float* W = phase ? W1 : W0;
        const __half* Ah = phase ? (layer ? g_hpreh : g_xh) : g_aggh;
#pragma unroll
        for (int j = 0; j < 2; ++j) {
            int idx = tid + j * 256;
            int m = idx >> 2;
            int kq = (idx & 3) * 4;
            int gr = row0 + m;
            float4 v = make_float4(0.f, 0.f, 0.f, 0.f);
            if (gr < nrows) {
                uint2 hv = *(const uint2*)(Ah + (size_t)gr * 128 + k0 + kq);
                float2 f0 = __half22float2(*reinterpret_cast<__half2*>(&hv.x));
                float2 f1 = __half22float2(*reinterpret_cast<__half2*>(&hv.y));
                v = make_float4(f0.x, f0.y, f1.x, f1.y);
                if (phase && layer) {
                    float4 gg = *(const float4*)&lnGamma[k0 + kq];
                    float4 bb = *(const float4*)&lnBeta[k0 + kq];
                    v.x = fmaxf((v.x - mu) * rstd * gg.x + bb.x, 0.f);
                    v.y = fmaxf((v.y - mu) * rstd * gg.y + bb.y, 0.f);
                    v.z = fmaxf((v.z - mu) * rstd * gg.z + bb.z, 0.f);
                    v.w = fmaxf((v.w - mu) * rstd * gg.w + bb.w, 0.f);
                }
            }
            va[j] = v;
            int kw = idx >> 5;
            int c4 = idx & 31;
            wv[j] = *(const float4*)(W + (size_t)(k0 + kw) * 128 + c4 * 4);
        }
    };

    auto store_tile = [&](int buf, bool cvtA) {
#pragma unroll
        for (int j = 0; j < 2; ++j) {
            int idx = tid + j * 256;
            int m = idx >> 2;
            int kq = (idx & 3) * 4;
            if (cvtA) {
                As[buf][kq + 0][m] = tf32f(va[j].x);
                As[buf][kq + 1][m] = tf32f(va[j].y);
                As[buf][kq + 2][m] = tf32f(va[j].z);
                As[buf][kq + 3][m] = tf32f(va[j].w);
            } else {
                As[buf][kq + 0][m] = va[j].x;
                As[buf][kq + 1][m] = va[j].y;
                As[buf][kq + 2][m] = va[j].z;
                As[buf][kq + 3][m] = va[j].w;
            }
            int kw = idx >> 5;
            int c4 = idx & 31;
            float4 wt;
            wt.x = tf32f(wv[j].x);
            wt.y = tf32f(wv[j].y);
            wt.z = tf32f(wv[j].z);
            wt.w = tf32f(wv[j].w);
            *(float4*)&Ws[buf][kw][c4 * 4] = wt;
        }
    };

    // A needs tf32 cvt only when LN was applied in-register (layer-2 phase 1).
    auto needsCvt = [&](int t) { return (t >> 3) && layer; };

    load_tile(0);
    store_tile(0, needsCvt(0));
    __syncthreads();

    for (int t = 0; t < NTILES; ++t) {
        int buf = t & 1;
        if (t < NTILES - 1) load_tile(t + 1);
#pragma unroll
        for (int ks = 0; ks < 16; ks += 8) {
            uint32_t af[2][4];
#pragma unroll
            for (int mt = 0; mt < 2; mt++) {
                int r = wm + mt * 16 + g;
                af[mt][0] = __float_as_uint(As[buf][ks + c][r]);
                af[mt][1] = __float_as_uint(As[buf][ks + c][r + 8]);
                af[mt][2] = __float_as_uint(As[buf][ks + c + 4][r]);
                af[mt][3] = __float_as_uint(As[buf][ks + c + 4][r + 8]);
            }
            uint32_t bf[8][2];
#pragma unroll
            for (int nt = 0; nt < 8; nt++) {
                int n = wn + nt * 8 + g;
                bf[nt][0] = __float_as_uint(Ws[buf][ks + c][n]);
                bf[nt][1] = __float_as_uint(Ws[buf][ks + c + 4][n]);
            }
#pragma unroll
            for (int mt = 0; mt < 2; mt++)
#pragma unroll
                for (int nt = 0; nt < 8; nt++)
                    mma_tf32(acc[mt][nt][0], acc[mt][nt][1],
                             acc[mt][nt][2], acc[mt][nt][3],
                             af[mt][0], af[mt][1], af[mt][2], af[mt][3],
                             bf[nt][0], bf[nt][1]);
        }
        if (t < NTILES - 1) store_tile(buf ^ 1, needsCvt(t + 1));
        __syncthreads();
    }

    // Epilogue: bias + fp16 store + LN stats
    float s = 0.f, sq = 0.f;
#pragma unroll
    for (int mt = 0; mt < 2; mt++) {
        int r0g = row0 + wm + mt * 16 + g;
#pragma unroll
        for (int nt = 0; nt < 8; nt++) {
            int col = wn + nt * 8 + 2 * c;
            float2 bj = *(const float2*)&bias[col];
            float v0 = acc[mt][nt][0] + bj.x;
            float v1 = acc[mt][nt][1] + bj.y;
            float v2 = acc[mt][nt][2] + bj.x;
            float v3 = acc[mt][nt][3] + bj.y;
            if (r0g < nrows) {
                __half2 hv = __floats2half2_rn(v0, v1);
                *(__half2*)&g_hpreh[(size_t)r0g * 128 + col] = hv;
                s += v0 + v1;
                sq += v0 * v0 + v1 * v1;
            }
            if (r0g + 8 < nrows) {
                __half2 hv = __floats2half2_rn(v2, v3);
                *(__half2*)&g_hpreh[(size_t)(r0g + 8) * 128 + col] = hv;
                s += v2 + v3;
                sq += v2 * v2 + v3 * v3;
            }
        }
    }

    __syncthreads();
    red[tid] = (double)s;
    __syncthreads();
    for (int off = 128; off; off >>= 1) {
        if (tid < off) red[tid] += red[tid + off];
        __syncthreads();
    }
    if (tid == 0) atomicAdd(&g_stats[statsBase + 0], red[0]);
    __syncthreads();
    red[tid] = (double)sq;
    __syncthreads();
    for (int off = 128; off; off >>= 1) {
        if (tid < off) red[tid] += red[tid + off];
        __syncthreads();
    }
    if (tid == 0) atomicAdd(&g_stats[statsBase + 1], red[0]);
}

// ---------------------------------------------------------------------------
// Final LN apply + ReLU + residual -> fp32 out (layer 2 only).
// ---------------------------------------------------------------------------
__global__ void ln_apply_kernel(const float* __restrict__ gamma,
                                const float* __restrict__ beta,
                                int statsBase,
                                const float* __restrict__ residual,
                                float* __restrict__ outExt,
                                long long total)
{
    double cntd = (double)total;
    double mu = g_stats[statsBase + 0] / cntd;
    double var = g_stats[statsBase + 1] / cntd - mu * mu;
    float rstd = (float)rsqrt(var + 1e-5);
    float fmu = (float)mu;

    long long n4 = total >> 2;
    long long i = (long long)blockIdx.x * blockDim.x + threadIdx.x;
    long long stride = (long long)gridDim.x * blockDim.x;

    for (long long t = i; t < n4; t += stride) {
        int cg = (int)(t & 31);
        float4 g = ((const float4*)gamma)[cg];
        float4 b = ((const float4*)beta)[cg];
        uint2 hu = ((const uint2*)g_hpreh)[t];
        float2 h0 = __half22float2(*reinterpret_cast<__half2*>(&hu.x));
        float2 h1 = __half22float2(*reinterpret_cast<__half2*>(&hu.y));
        float4 r = ((const float4*)residual)[t];
        float4 v;
        v.x = fmaxf((h0.x - fmu) * rstd * g.x + b.x, 0.f) + r.x;
        v.y = fmaxf((h0.y - fmu) * rstd * g.y + b.y, 0.f) + r.y;
        v.z = fmaxf((h1.x - fmu) * rstd * g.z + b.z, 0.f) + r.z;
        v.w = fmaxf((h1.y - fmu) * rstd * g.w + b.w, 0.f) + r.w;
        ((float4*)outExt)[t] = v;
    }
}

// ---------------------------------------------------------------------------
extern "C" void kernel_launch(void* const* d_in, const int* in_sizes, int n_in,
                              void* d_out, int out_size)
{
    const float* x   = (const float*)d_in[0];
    const int*   ei  = (const int*)d_in[1];   // int32
    const float* Wl1 = (const float*)d_in[2];
    const float* bl1 = (const float*)d_in[3];
    const float* Wr1 = (const float*)d_in[4];
    const float* g1  = (const float*)d_in[5];
    const float* b1  = (const float*)d_in[6];
    const float* Wl2 = (const float*)d_in[7];
    const float* bl2 = (const float*)d_in[8];
    const float* Wr2 = (const float*)d_in[9];
    const float* g2  = (const float*)d_in[10];
    const float* b2  = (const float*)d_in[11];

    int E = in_sizes[1] / 2;
    int nrows = in_sizes[0] / CC;
    long long total = (long long)nrows * CC;

    const int* src = ei;
    const int* dst = ei + E;

    int eBlocks    = (E + 255) / 256;
    int aggBlocks  = (nrows + 7) / 8;
    int gemmBlocks = (nrows + 127) / 128;
    int lnBlocks   = (int)((total / 4 + 255) / 256);
    int scanBlocks = (nrows + SCAN_BLK - 1) / SCAN_BLK;

    // ---- CSR build + x->half ----
    init_kernel<<<1024, 256>>>(x, total / 4, nrows);
    hist_kernel<<<eBlocks, 256>>>(dst, E, nrows);
    scan1_kernel<<<scanBlocks, SCAN_BLK>>>(nrows);
    scan2_kernel<<<1, SCAN_BLK>>>(scanBlocks, nrows);
    scan3_kernel<<<scanBlocks, SCAN_BLK>>>(nrows);
    fill_kernel<<<eBlocks, 256>>>(src, dst, E, nrows);

    // ---- Layer 1 ----
    agg_kernel<<<aggBlocks, 256>>>(nrows, 0, nullptr, nullptr);
    gemm_ln_kernel<<<gemmBlocks, 256>>>(Wl1, Wr1, bl1, nullptr, nullptr, 0, nrows, 0);
    finalize_kernel<<<1, 32>>>(total);

    // ---- Layer 2 (LN1+ReLU fused into consumers) ----
    agg_kernel<<<aggBlocks, 256>>>(nrows, 1, g1, b1);
    gemm_ln_kernel<<<gemmBlocks, 256>>>(Wl2, Wr2, bl2, g1, b1, 2, nrows, 1);
    ln_apply_kernel<<<lnBlocks, 256>>>(g2, b2, 2, x, (float*)d_out, total);
}